// round 10
// baseline (speedup 1.0000x reference)
#include <cuda_runtime.h>
#include <cuda_bf16.h>
#include <math.h>

// Problem constants
#define CB   8
#define CS   4096
#define CD   512
#define CP   128
#define CL   4
#define CDF  2048
#define CDH  256
#define CC   2
#define CBS  (CB*CS)          // 32768 tokens

#define KVSPLIT 8
#define PKCH    32
#define POOLCH  16

// ---------------- scratch (device globals; no allocation allowed) ----------------
__device__ float g_h   [(size_t)CBS*CD];
__device__ float g_q   [(size_t)CBS*CD];
__device__ float g_k   [(size_t)CBS*CD];
__device__ float g_v   [(size_t)CBS*CD];
__device__ float g_a   [(size_t)CBS*CD];
__device__ float g_pq  [(size_t)CBS*CP];
__device__ float g_pk  [(size_t)CBS*CP];
__device__ float g_mlp [(size_t)CBS*CDF];
__device__ float g_kv  [(size_t)CB*CP*CD];
__device__ float g_kvp [(size_t)CB*KVSPLIT*CP*CD];
__device__ float g_pks [(size_t)CB*CP];
__device__ float g_pkp [(size_t)PKCH*CB*CP];
__device__ float g_z   [(size_t)CBS];
__device__ float g_pool[(size_t)CB*CD];
__device__ float g_poolp[(size_t)POOLCH*CB*CD];
__device__ float g_h1  [(size_t)CB*CDH];

// ---------------- embedding ----------------
__global__ void embed_kernel(const int* __restrict__ x,
                             const float* __restrict__ emb,
                             const float* __restrict__ pos)
{
    long row = blockIdx.x;                // 0..CBS-1
    int  s   = (int)(row & (CS - 1));
    int  tok = x[row];
    int  t   = threadIdx.x;               // 128 threads, float4 each
    float4 e = ((const float4*)(emb + (long)tok * CD))[t];
    float4 p = ((const float4*)(pos + (long)s   * CD))[t];
    ((float4*)(g_h + row * CD))[t] = make_float4(e.x+p.x, e.y+p.y, e.z+p.z, e.w+p.w);
}

// ---------------- generic NN SGEMM, 128x128x8, epilogues ----------------
// EPI: 0 = +bias ; 1 = elu(+bias)+1 ; 2 = tanh-gelu(+bias) ; 3 = /(z+1e-6), no bias
template<int EPI>
__global__ __launch_bounds__(256)
void sgemm_nn(const float* __restrict__ A, const float* __restrict__ W,
              const float* __restrict__ bias, float* __restrict__ Cc,
              int M, int N, int K,
              long sA, long sB, long sC,
              const float* __restrict__ zvec)
{
    const int bz = blockIdx.z;
    A  += (long)bz * sA;
    W  += (long)bz * sB;
    Cc += (long)bz * sC;

    __shared__ float As[8][128];
    __shared__ float Bs[8][128];

    const int tid  = threadIdx.x;
    const int brow = blockIdx.y * 128;
    const int bcol = blockIdx.x * 128;

    const int aRow = tid >> 1;
    const int aCol = (tid & 1) << 2;
    const int bRow = tid >> 5;
    const int bCol = (tid & 31) << 2;

    const int mBase = (tid >> 4) << 3;
    const int nBase = (tid & 15) << 3;

    float acc[8][8];
    #pragma unroll
    for (int i = 0; i < 8; i++)
        #pragma unroll
        for (int j = 0; j < 8; j++) acc[i][j] = 0.f;

    const float* Ap = A + (long)(brow + aRow) * K + aCol;
    const float* Bp = W + (long)bRow * N + bcol + bCol;

    for (int k0 = 0; k0 < K; k0 += 8) {
        float4 av = *(const float4*)(Ap + k0);
        As[aCol+0][aRow] = av.x;
        As[aCol+1][aRow] = av.y;
        As[aCol+2][aRow] = av.z;
        As[aCol+3][aRow] = av.w;
        float4 bv = *(const float4*)(Bp + (long)k0 * N);
        *(float4*)&Bs[bRow][bCol] = bv;
        __syncthreads();
        #pragma unroll
        for (int k = 0; k < 8; k++) {
            float4 a0 = *(const float4*)&As[k][mBase];
            float4 a1 = *(const float4*)&As[k][mBase+4];
            float4 b0 = *(const float4*)&Bs[k][nBase];
            float4 b1 = *(const float4*)&Bs[k][nBase+4];
            float ra[8] = {a0.x,a0.y,a0.z,a0.w,a1.x,a1.y,a1.z,a1.w};
            float rb[8] = {b0.x,b0.y,b0.z,b0.w,b1.x,b1.y,b1.z,b1.w};
            #pragma unroll
            for (int i = 0; i < 8; i++)
                #pragma unroll
                for (int j = 0; j < 8; j++)
                    acc[i][j] = fmaf(ra[i], rb[j], acc[i][j]);
        }
        __syncthreads();
    }

    float bvals[8];
    #pragma unroll
    for (int j = 0; j < 8; j++)
        bvals[j] = (EPI == 3) ? 0.f : bias[bcol + nBase + j];

    #pragma unroll
    for (int i = 0; i < 8; i++) {
        const int m = brow + mBase + i;
        float zin = 1.f;
        if (EPI == 3) zin = 1.f / (zvec[(long)bz * CS + m] + 1e-6f);
        float outv[8];
        #pragma unroll
        for (int j = 0; j < 8; j++) {
            float v = acc[i][j] + bvals[j];
            if (EPI == 1) {
                v = (v > 0.f) ? (v + 1.f) : expf(v);
            } else if (EPI == 2) {
                float u = 0.7978845608028654f * (v + 0.044715f * v * v * v);
                v = 0.5f * v * (1.f + tanhf(u));
            } else if (EPI == 3) {
                v = v * zin;
            }
            outv[j] = v;
        }
        float4* cp = (float4*)(Cc + (long)m * N + bcol + nBase);
        cp[0] = make_float4(outv[0], outv[1], outv[2], outv[3]);
        cp[1] = make_float4(outv[4], outv[5], outv[6], outv[7]);
    }
}

// ---------------- TN SGEMM for kv = pk^T @ v, deterministic split-K ----------------
// C_part[b*KVSPLIT+split][p][d] = sum_{s in chunk} pk[b][s][p] * v[b][s][d]
__global__ __launch_bounds__(256)
void sgemm_tn_split(void)
{
    const int bz    = blockIdx.z;          // b*KVSPLIT + split
    const int b     = bz / KVSPLIT;
    const int split = bz % KVSPLIT;
    const int kBeg  = split * (CS / KVSPLIT);

    const float* A  = g_pk + (long)b * CS * CP;   // [S][P]
    const float* Bm = g_v  + (long)b * CS * CD;   // [S][D]
    float*       Cc = g_kvp + (long)bz * CP * CD;

    const int tid  = threadIdx.x;
    const int bcol = blockIdx.x * 128;     // within D

    __shared__ float As[8][128];
    __shared__ float Bs[8][128];

    const int lRow = tid >> 5;             // k in tile (0..7)
    const int lCol = (tid & 31) << 2;

    const int mBase = (tid >> 4) << 3;
    const int nBase = (tid & 15) << 3;

    float acc[8][8];
    #pragma unroll
    for (int i = 0; i < 8; i++)
        #pragma unroll
        for (int j = 0; j < 8; j++) acc[i][j] = 0.f;

    for (int k0 = 0; k0 < CS / KVSPLIT; k0 += 8) {
        const long kk = kBeg + k0 + lRow;
        *(float4*)&As[lRow][lCol] = *(const float4*)(A  + kk * CP + lCol);
        *(float4*)&Bs[lRow][lCol] = *(const float4*)(Bm + kk * CD + bcol + lCol);
        __syncthreads();
        #pragma unroll
        for (int k = 0; k < 8; k++) {
            float4 a0 = *(const float4*)&As[k][mBase];
            float4 a1 = *(const float4*)&As[k][mBase+4];
            float4 b0 = *(const float4*)&Bs[k][nBase];
            float4 b1 = *(const float4*)&Bs[k][nBase+4];
            float ra[8] = {a0.x,a0.y,a0.z,a0.w,a1.x,a1.y,a1.z,a1.w};
            float rb[8] = {b0.x,b0.y,b0.z,b0.w,b1.x,b1.y,b1.z,b1.w};
            #pragma unroll
            for (int i = 0; i < 8; i++)
                #pragma unroll
                for (int j = 0; j < 8; j++)
                    acc[i][j] = fmaf(ra[i], rb[j], acc[i][j]);
        }
        __syncthreads();
    }

    #pragma unroll
    for (int i = 0; i < 8; i++) {
        float4* cp = (float4*)(Cc + (long)(mBase + i) * CD + bcol + nBase);
        cp[0] = make_float4(acc[i][0], acc[i][1], acc[i][2], acc[i][3]);
        cp[1] = make_float4(acc[i][4], acc[i][5], acc[i][6], acc[i][7]);
    }
}

__global__ void kv_reduce_kernel(void)
{
    long idx = (long)blockIdx.x * blockDim.x + threadIdx.x;   // over CB*CP*CD
    if (idx >= (long)CB * CP * CD) return;
    long b = idx / (CP * CD);
    long r = idx % (CP * CD);
    float s = 0.f;
    #pragma unroll
    for (int sp = 0; sp < KVSPLIT; sp++)
        s += g_kvp[(b * KVSPLIT + sp) * (long)(CP * CD) + r];
    g_kv[idx] = s;
}

// ---------------- pk.sum over S ----------------
__global__ void pksum_part_kernel(void)   // grid (CB, PKCH), block 128
{
    int b = blockIdx.x, ch = blockIdx.y, t = threadIdx.x;
    const int chunk = CS / PKCH;
    float acc = 0.f;
    const float* p = g_pk + ((long)b * CS + (long)ch * chunk) * CP + t;
    for (int s = 0; s < chunk; s++) acc += p[(long)s * CP];
    g_pkp[((long)ch * CB + b) * CP + t] = acc;
}

__global__ void pksum_reduce_kernel(void)
{
    int idx = blockIdx.x * blockDim.x + threadIdx.x;
    if (idx >= CB * CP) return;
    float s = 0.f;
    #pragma unroll
    for (int ch = 0; ch < PKCH; ch++)
        s += g_pkp[(long)ch * CB * CP + idx];
    g_pks[idx] = s;
}

// ---------------- z = pq . pksum (per row) ----------------
__global__ void z_kernel(void)   // grid CBS/8, block 256 (8 warps)
{
    const long row  = (long)blockIdx.x * 8 + (threadIdx.x >> 5);
    const int  lane = threadIdx.x & 31;
    const int  b    = (int)(row / CS);
    const float* pr = g_pq  + row * CP;
    const float* ps = g_pks + (long)b * CP;
    float acc = 0.f;
    #pragma unroll
    for (int i = lane; i < CP; i += 32) acc += pr[i] * ps[i];
    #pragma unroll
    for (int o = 16; o; o >>= 1) acc += __shfl_xor_sync(0xffffffffu, acc, o);
    if (lane == 0) g_z[row] = acc;
}

// ---------------- layernorm, in-place, one 128-thread block per row ----------------
__global__ void ln_kernel(float* __restrict__ X,
                          const float* __restrict__ gamma,
                          const float* __restrict__ beta)
{
    __shared__ float red[128];
    const long row = blockIdx.x;
    float4* xp = (float4*)(X + row * CD);
    const int t = threadIdx.x;
    float4 v = xp[t];

    red[t] = v.x + v.y + v.z + v.w;
    __syncthreads();
    for (int o = 64; o; o >>= 1) { if (t < o) red[t] += red[t + o]; __syncthreads(); }
    const float mu = red[0] * (1.f / CD);
    __syncthreads();

    float dx = v.x - mu, dy = v.y - mu, dz = v.z - mu, dw = v.w - mu;
    red[t] = dx*dx + dy*dy + dz*dz + dw*dw;
    __syncthreads();
    for (int o = 64; o; o >>= 1) { if (t < o) red[t] += red[t + o]; __syncthreads(); }
    const float rstd = rsqrtf(red[0] * (1.f / CD) + 1e-5f);

    const float4 g4 = ((const float4*)gamma)[t];
    const float4 b4 = ((const float4*)beta)[t];
    float4 o;
    o.x = dx * rstd * g4.x + b4.x;
    o.y = dy * rstd * g4.y + b4.y;
    o.z = dz * rstd * g4.z + b4.z;
    o.w = dw * rstd * g4.w + b4.w;
    xp[t] = o;
}

// ---------------- mean pool over S ----------------
__global__ void pool_part_kernel(void)    // grid (CB, POOLCH), block CD
{
    int b = blockIdx.x, ch = blockIdx.y, d = threadIdx.x;
    const int chunk = CS / POOLCH;
    float acc = 0.f;
    const float* p = g_h + ((long)b * CS + (long)ch * chunk) * CD + d;
    for (int s = 0; s < chunk; s++) acc += p[(long)s * CD];
    g_poolp[((long)ch * CB + b) * CD + d] = acc;
}

__global__ void pool_reduce_kernel(void)
{
    int idx = blockIdx.x * blockDim.x + threadIdx.x;
    if (idx >= CB * CD) return;
    float s = 0.f;
    #pragma unroll
    for (int ch = 0; ch < POOLCH; ch++)
        s += g_poolp[(long)ch * CB * CD + idx];
    g_pool[idx] = s * (1.f / CS);
}

// ---------------- head ----------------
__global__ void head1_kernel(const float* __restrict__ Wh1,
                             const float* __restrict__ bh1)
{
    int b = blockIdx.x, t = threadIdx.x;       // block = CDH threads
    const float* pr = g_pool + (long)b * CD;
    float acc = 0.f;
    for (int k = 0; k < CD; k++)
        acc = fmaf(pr[k], Wh1[(long)k * CDH + t], acc);
    float v = acc + bh1[t];
    g_h1[(long)b * CDH + t] = v > 0.f ? v : 0.f;
}

__global__ void head2_kernel(const float* __restrict__ Wh2,
                             const float* __restrict__ bh2,
                             float* __restrict__ out)
{
    int idx = threadIdx.x;
    if (idx >= CB * CC) return;
    int b = idx / CC, c = idx % CC;
    const float* h1 = g_h1 + (long)b * CDH;
    float acc = 0.f;
    for (int k = 0; k < CDH; k++)
        acc = fmaf(h1[k], Wh2[(long)k * CC + c], acc);
    out[idx] = acc + bh2[c];
}

// ---------------- host ----------------
extern "C" void kernel_launch(void* const* d_in, const int* in_sizes, int n_in,
                              void* d_out, int out_size)
{
    (void)in_sizes; (void)n_in; (void)out_size;

    const int*   x    = (const int*)  d_in[0];
    const float* emb  = (const float*)d_in[1];
    const float* pos  = (const float*)d_in[2];
    const float* Wq   = (const float*)d_in[3];
    const float* bq   = (const float*)d_in[4];
    const float* Wk   = (const float*)d_in[5];
    const float* bk   = (const float*)d_in[6];
    const float* Wv   = (const float*)d_in[7];
    const float* bv   = (const float*)d_in[8];
    const float* Wf   = (const float*)d_in[9];
    const float* bf   = (const float*)d_in[10];
    const float* Wo   = (const float*)d_in[11];
    const float* bo   = (const float*)d_in[12];
    const float* lng  = (const float*)d_in[13];
    const float* lnb  = (const float*)d_in[14];
    const float* W1   = (const float*)d_in[15];
    const float* b1   = (const float*)d_in[16];
    const float* W2   = (const float*)d_in[17];
    const float* b2   = (const float*)d_in[18];
    const float* Wh1  = (const float*)d_in[19];
    const float* bh1  = (const float*)d_in[20];
    const float* Wh2  = (const float*)d_in[21];
    const float* bh2  = (const float*)d_in[22];
    float* out = (float*)d_out;

    float *ph, *pq, *pk, *pv, *pa, *ppq, *ppk, *pmlp, *pkv, *pz;
    cudaGetSymbolAddress((void**)&ph,   g_h);
    cudaGetSymbolAddress((void**)&pq,   g_q);
    cudaGetSymbolAddress((void**)&pk,   g_k);
    cudaGetSymbolAddress((void**)&pv,   g_v);
    cudaGetSymbolAddress((void**)&pa,   g_a);
    cudaGetSymbolAddress((void**)&ppq,  g_pq);
    cudaGetSymbolAddress((void**)&ppk,  g_pk);
    cudaGetSymbolAddress((void**)&pmlp, g_mlp);
    cudaGetSymbolAddress((void**)&pkv,  g_kv);
    cudaGetSymbolAddress((void**)&pz,   g_z);

    embed_kernel<<<CBS, 128>>>(x, emb, pos);

    for (int l = 0; l < CL; l++) {
        const float* wq = Wq + (long)l * CD * CD;
        const float* wk = Wk + (long)l * CD * CD;
        const float* wv = Wv + (long)l * CD * CD;
        const float* wf = Wf + (long)l * CD * CP;
        const float* wo = Wo + (long)l * CD * CD;
        const float* w1 = W1 + (long)l * CD * CDF;
        const float* w2 = W2 + (long)l * CDF * CD;
        const float* biq = bq + (long)l * CD;
        const float* bik = bk + (long)l * CD;
        const float* biv = bv + (long)l * CD;
        const float* bif = bf + (long)l * CP;
        const float* bio = bo + (long)l * CD;
        const float* bi1 = b1 + (long)l * CDF;
        const float* bi2 = b2 + (long)l * CD;

        dim3 gQKV(CD / 128, CBS / 128, 1);
        sgemm_nn<0><<<gQKV, 256>>>(ph, wq, biq, pq, CBS, CD, CD, 0, 0, 0, nullptr);
        sgemm_nn<0><<<gQKV, 256>>>(ph, wk, bik, pk, CBS, CD, CD, 0, 0, 0, nullptr);
        sgemm_nn<0><<<gQKV, 256>>>(ph, wv, biv, pv, CBS, CD, CD, 0, 0, 0, nullptr);

        dim3 gF(CP / 128, CBS / 128, 1);
        sgemm_nn<1><<<gF, 256>>>(pq, wf, bif, ppq, CBS, CP, CD, 0, 0, 0, nullptr);
        sgemm_nn<1><<<gF, 256>>>(pk, wf, bif, ppk, CBS, CP, CD, 0, 0, 0, nullptr);

        pksum_part_kernel<<<dim3(CB, PKCH), 128>>>();
        pksum_reduce_kernel<<<(CB * CP + 255) / 256, 256>>>();

        sgemm_tn_split<<<dim3(CD / 128, 1, CB * KVSPLIT), 256>>>();
        kv_reduce_kernel<<<(CB * CP * CD + 255) / 256, 256>>>();

        z_kernel<<<CBS / 8, 256>>>();

        // out[b,s,d] = (pq @ kv) / (z + eps)   (batched)
        dim3 gO(CD / 128, CS / 128, CB);
        sgemm_nn<3><<<gO, 256>>>(ppq, pkv, nullptr, pa,
                                 CS, CD, CP,
                                 (long)CS * CP, (long)CP * CD, (long)CS * CD, pz);

        sgemm_nn<0><<<gQKV, 256>>>(pa, wo, bio, pq, CBS, CD, CD, 0, 0, 0, nullptr);

        ln_kernel<<<CBS, 128>>>(pq, lng + (long)l * CD, lnb + (long)l * CD);

        dim3 g1(CDF / 128, CBS / 128, 1);
        sgemm_nn<2><<<g1, 256>>>(pq, w1, bi1, pmlp, CBS, CDF, CD, 0, 0, 0, nullptr);

        dim3 g2(CD / 128, CBS / 128, 1);
        sgemm_nn<0><<<g2, 256>>>(pmlp, w2, bi2, ph, CBS, CD, CDF, 0, 0, 0, nullptr);
    }

    pool_part_kernel<<<dim3(CB, POOLCH), CD>>>();
    pool_reduce_kernel<<<(CB * CD + 255) / 256, 256>>>();
    head1_kernel<<<CB, CDH>>>(Wh1, bh1);
    head2_kernel<<<1, 32>>>(Wh2, bh2, out);
}

// round 11
// speedup vs baseline: 1.0007x; 1.0007x over previous
#include <cuda_runtime.h>
#include <cuda_bf16.h>
#include <math.h>

// Problem constants
#define CB   8
#define CS   4096
#define CD   512
#define CP   128
#define CL   4
#define CDF  2048
#define CDH  256
#define CC   2
#define CBS  (CB*CS)          // 32768 tokens

#define KVSPLIT 8
#define PKCH    32
#define POOLCH  16

// ---------------- scratch (device globals; no allocation allowed) ----------------
__device__ float g_h   [(size_t)CBS*CD];
__device__ float g_q   [(size_t)CBS*CD];
__device__ float g_k   [(size_t)CBS*CD];
__device__ float g_v   [(size_t)CBS*CD];
__device__ float g_a   [(size_t)CBS*CD];
__device__ float g_pq  [(size_t)CBS*CP];
__device__ float g_pk  [(size_t)CBS*CP];
__device__ float g_mlp [(size_t)CBS*CDF];
__device__ float g_kv  [(size_t)CB*CP*CD];
__device__ float g_kvp [(size_t)CB*KVSPLIT*CP*CD];
__device__ float g_pks [(size_t)CB*CP];
__device__ float g_pkp [(size_t)PKCH*CB*CP];
__device__ float g_z   [(size_t)CBS];
__device__ float g_pool[(size_t)CB*CD];
__device__ float g_poolp[(size_t)POOLCH*CB*CD];
__device__ float g_h1  [(size_t)CB*CDH];

// ---------------- embedding ----------------
__global__ void embed_kernel(const int* __restrict__ x,
                             const float* __restrict__ emb,
                             const float* __restrict__ pos)
{
    long row = blockIdx.x;                // 0..CBS-1
    int  s   = (int)(row & (CS - 1));
    int  tok = x[row];
    int  t   = threadIdx.x;               // 128 threads, float4 each
    float4 e = ((const float4*)(emb + (long)tok * CD))[t];
    float4 p = ((const float4*)(pos + (long)s   * CD))[t];
    ((float4*)(g_h + row * CD))[t] = make_float4(e.x+p.x, e.y+p.y, e.z+p.z, e.w+p.w);
}

// ---------------- generic NN SGEMM, 128x128x8, epilogues ----------------
// EPI: 0 = +bias ; 1 = elu(+bias)+1 ; 2 = tanh-gelu(+bias) ; 3 = /(z+1e-6), no bias
template<int EPI>
__global__ __launch_bounds__(256)
void sgemm_nn(const float* __restrict__ A, const float* __restrict__ W,
              const float* __restrict__ bias, float* __restrict__ Cc,
              int M, int N, int K,
              long sA, long sB, long sC,
              const float* __restrict__ zvec)
{
    const int bz = blockIdx.z;
    A  += (long)bz * sA;
    W  += (long)bz * sB;
    Cc += (long)bz * sC;

    __shared__ float As[8][128];
    __shared__ float Bs[8][128];

    const int tid  = threadIdx.x;
    const int brow = blockIdx.y * 128;
    const int bcol = blockIdx.x * 128;

    const int aRow = tid >> 1;
    const int aCol = (tid & 1) << 2;
    const int bRow = tid >> 5;
    const int bCol = (tid & 31) << 2;

    const int mBase = (tid >> 4) << 3;
    const int nBase = (tid & 15) << 3;

    float acc[8][8];
    #pragma unroll
    for (int i = 0; i < 8; i++)
        #pragma unroll
        for (int j = 0; j < 8; j++) acc[i][j] = 0.f;

    const float* Ap = A + (long)(brow + aRow) * K + aCol;
    const float* Bp = W + (long)bRow * N + bcol + bCol;

    for (int k0 = 0; k0 < K; k0 += 8) {
        float4 av = *(const float4*)(Ap + k0);
        As[aCol+0][aRow] = av.x;
        As[aCol+1][aRow] = av.y;
        As[aCol+2][aRow] = av.z;
        As[aCol+3][aRow] = av.w;
        float4 bv = *(const float4*)(Bp + (long)k0 * N);
        *(float4*)&Bs[bRow][bCol] = bv;
        __syncthreads();
        #pragma unroll
        for (int k = 0; k < 8; k++) {
            float4 a0 = *(const float4*)&As[k][mBase];
            float4 a1 = *(const float4*)&As[k][mBase+4];
            float4 b0 = *(const float4*)&Bs[k][nBase];
            float4 b1 = *(const float4*)&Bs[k][nBase+4];
            float ra[8] = {a0.x,a0.y,a0.z,a0.w,a1.x,a1.y,a1.z,a1.w};
            float rb[8] = {b0.x,b0.y,b0.z,b0.w,b1.x,b1.y,b1.z,b1.w};
            #pragma unroll
            for (int i = 0; i < 8; i++)
                #pragma unroll
                for (int j = 0; j < 8; j++)
                    acc[i][j] = fmaf(ra[i], rb[j], acc[i][j]);
        }
        __syncthreads();
    }

    float bvals[8];
    #pragma unroll
    for (int j = 0; j < 8; j++)
        bvals[j] = (EPI == 3) ? 0.f : bias[bcol + nBase + j];

    #pragma unroll
    for (int i = 0; i < 8; i++) {
        const int m = brow + mBase + i;
        float zin = 1.f;
        if (EPI == 3) zin = 1.f / (zvec[(long)bz * CS + m] + 1e-6f);
        float outv[8];
        #pragma unroll
        for (int j = 0; j < 8; j++) {
            float v = acc[i][j] + bvals[j];
            if (EPI == 1) {
                v = (v > 0.f) ? (v + 1.f) : expf(v);
            } else if (EPI == 2) {
                float u = 0.7978845608028654f * (v + 0.044715f * v * v * v);
                v = 0.5f * v * (1.f + tanhf(u));
            } else if (EPI == 3) {
                v = v * zin;
            }
            outv[j] = v;
        }
        float4* cp = (float4*)(Cc + (long)m * N + bcol + nBase);
        cp[0] = make_float4(outv[0], outv[1], outv[2], outv[3]);
        cp[1] = make_float4(outv[4], outv[5], outv[6], outv[7]);
    }
}

// ---------------- TN SGEMM for kv = pk^T @ v, deterministic split-K ----------------
// C_part[b*KVSPLIT+split][p][d] = sum_{s in chunk} pk[b][s][p] * v[b][s][d]
__global__ __launch_bounds__(256)
void sgemm_tn_split(void)
{
    const int bz    = blockIdx.z;          // b*KVSPLIT + split
    const int b     = bz / KVSPLIT;
    const int split = bz % KVSPLIT;
    const int kBeg  = split * (CS / KVSPLIT);

    const float* A  = g_pk + (long)b * CS * CP;   // [S][P]
    const float* Bm = g_v  + (long)b * CS * CD;   // [S][D]
    float*       Cc = g_kvp + (long)bz * CP * CD;

    const int tid  = threadIdx.x;
    const int bcol = blockIdx.x * 128;     // within D

    __shared__ float As[8][128];
    __shared__ float Bs[8][128];

    const int lRow = tid >> 5;             // k in tile (0..7)
    const int lCol = (tid & 31) << 2;

    const int mBase = (tid >> 4) << 3;
    const int nBase = (tid & 15) << 3;

    float acc[8][8];
    #pragma unroll
    for (int i = 0; i < 8; i++)
        #pragma unroll
        for (int j = 0; j < 8; j++) acc[i][j] = 0.f;

    for (int k0 = 0; k0 < CS / KVSPLIT; k0 += 8) {
        const long kk = kBeg + k0 + lRow;
        *(float4*)&As[lRow][lCol] = *(const float4*)(A  + kk * CP + lCol);
        *(float4*)&Bs[lRow][lCol] = *(const float4*)(Bm + kk * CD + bcol + lCol);
        __syncthreads();
        #pragma unroll
        for (int k = 0; k < 8; k++) {
            float4 a0 = *(const float4*)&As[k][mBase];
            float4 a1 = *(const float4*)&As[k][mBase+4];
            float4 b0 = *(const float4*)&Bs[k][nBase];
            float4 b1 = *(const float4*)&Bs[k][nBase+4];
            float ra[8] = {a0.x,a0.y,a0.z,a0.w,a1.x,a1.y,a1.z,a1.w};
            float rb[8] = {b0.x,b0.y,b0.z,b0.w,b1.x,b1.y,b1.z,b1.w};
            #pragma unroll
            for (int i = 0; i < 8; i++)
                #pragma unroll
                for (int j = 0; j < 8; j++)
                    acc[i][j] = fmaf(ra[i], rb[j], acc[i][j]);
        }
        __syncthreads();
    }

    #pragma unroll
    for (int i = 0; i < 8; i++) {
        float4* cp = (float4*)(Cc + (long)(mBase + i) * CD + bcol + nBase);
        cp[0] = make_float4(acc[i][0], acc[i][1], acc[i][2], acc[i][3]);
        cp[1] = make_float4(acc[i][4], acc[i][5], acc[i][6], acc[i][7]);
    }
}

__global__ void kv_reduce_kernel(void)
{
    long idx = (long)blockIdx.x * blockDim.x + threadIdx.x;   // over CB*CP*CD
    if (idx >= (long)CB * CP * CD) return;
    long b = idx / (CP * CD);
    long r = idx % (CP * CD);
    float s = 0.f;
    #pragma unroll
    for (int sp = 0; sp < KVSPLIT; sp++)
        s += g_kvp[(b * KVSPLIT + sp) * (long)(CP * CD) + r];
    g_kv[idx] = s;
}

// ---------------- pk.sum over S ----------------
__global__ void pksum_part_kernel(void)   // grid (CB, PKCH), block 128
{
    int b = blockIdx.x, ch = blockIdx.y, t = threadIdx.x;
    const int chunk = CS / PKCH;
    float acc = 0.f;
    const float* p = g_pk + ((long)b * CS + (long)ch * chunk) * CP + t;
    for (int s = 0; s < chunk; s++) acc += p[(long)s * CP];
    g_pkp[((long)ch * CB + b) * CP + t] = acc;
}

__global__ void pksum_reduce_kernel(void)
{
    int idx = blockIdx.x * blockDim.x + threadIdx.x;
    if (idx >= CB * CP) return;
    float s = 0.f;
    #pragma unroll
    for (int ch = 0; ch < PKCH; ch++)
        s += g_pkp[(long)ch * CB * CP + idx];
    g_pks[idx] = s;
}

// ---------------- z = pq . pksum (per row) ----------------
__global__ void z_kernel(void)   // grid CBS/8, block 256 (8 warps)
{
    const long row  = (long)blockIdx.x * 8 + (threadIdx.x >> 5);
    const int  lane = threadIdx.x & 31;
    const int  b    = (int)(row / CS);
    const float* pr = g_pq  + row * CP;
    const float* ps = g_pks + (long)b * CP;
    float acc = 0.f;
    #pragma unroll
    for (int i = lane; i < CP; i += 32) acc += pr[i] * ps[i];
    #pragma unroll
    for (int o = 16; o; o >>= 1) acc += __shfl_xor_sync(0xffffffffu, acc, o);
    if (lane == 0) g_z[row] = acc;
}

// ---------------- layernorm, in-place, one 128-thread block per row ----------------
__global__ void ln_kernel(float* __restrict__ X,
                          const float* __restrict__ gamma,
                          const float* __restrict__ beta)
{
    __shared__ float red[128];
    const long row = blockIdx.x;
    float4* xp = (float4*)(X + row * CD);
    const int t = threadIdx.x;
    float4 v = xp[t];

    red[t] = v.x + v.y + v.z + v.w;
    __syncthreads();
    for (int o = 64; o; o >>= 1) { if (t < o) red[t] += red[t + o]; __syncthreads(); }
    const float mu = red[0] * (1.f / CD);
    __syncthreads();

    float dx = v.x - mu, dy = v.y - mu, dz = v.z - mu, dw = v.w - mu;
    red[t] = dx*dx + dy*dy + dz*dz + dw*dw;
    __syncthreads();
    for (int o = 64; o; o >>= 1) { if (t < o) red[t] += red[t + o]; __syncthreads(); }
    const float rstd = rsqrtf(red[0] * (1.f / CD) + 1e-5f);

    const float4 g4 = ((const float4*)gamma)[t];
    const float4 b4 = ((const float4*)beta)[t];
    float4 o;
    o.x = dx * rstd * g4.x + b4.x;
    o.y = dy * rstd * g4.y + b4.y;
    o.z = dz * rstd * g4.z + b4.z;
    o.w = dw * rstd * g4.w + b4.w;
    xp[t] = o;
}

// ---------------- mean pool over S ----------------
__global__ void pool_part_kernel(void)    // grid (CB, POOLCH), block CD
{
    int b = blockIdx.x, ch = blockIdx.y, d = threadIdx.x;
    const int chunk = CS / POOLCH;
    float acc = 0.f;
    const float* p = g_h + ((long)b * CS + (long)ch * chunk) * CD + d;
    for (int s = 0; s < chunk; s++) acc += p[(long)s * CD];
    g_poolp[((long)ch * CB + b) * CD + d] = acc;
}

__global__ void pool_reduce_kernel(void)
{
    int idx = blockIdx.x * blockDim.x + threadIdx.x;
    if (idx >= CB * CD) return;
    float s = 0.f;
    #pragma unroll
    for (int ch = 0; ch < POOLCH; ch++)
        s += g_poolp[(long)ch * CB * CD + idx];
    g_pool[idx] = s * (1.f / CS);
}

// ---------------- head ----------------
__global__ void head1_kernel(const float* __restrict__ Wh1,
                             const float* __restrict__ bh1)
{
    int b = blockIdx.x, t = threadIdx.x;       // block = CDH threads
    const float* pr = g_pool + (long)b * CD;
    float acc = 0.f;
    for (int k = 0; k < CD; k++)
        acc = fmaf(pr[k], Wh1[(long)k * CDH + t], acc);
    float v = acc + bh1[t];
    g_h1[(long)b * CDH + t] = v > 0.f ? v : 0.f;
}

__global__ void head2_kernel(const float* __restrict__ Wh2,
                             const float* __restrict__ bh2,
                             float* __restrict__ out)
{
    int idx = threadIdx.x;
    if (idx >= CB * CC) return;
    int b = idx / CC, c = idx % CC;
    const float* h1 = g_h1 + (long)b * CDH;
    float acc = 0.f;
    for (int k = 0; k < CDH; k++)
        acc = fmaf(h1[k], Wh2[(long)k * CC + c], acc);
    out[idx] = acc + bh2[c];
}

// ---------------- host ----------------
extern "C" void kernel_launch(void* const* d_in, const int* in_sizes, int n_in,
                              void* d_out, int out_size)
{
    (void)in_sizes; (void)n_in; (void)out_size;

    const int*   x    = (const int*)  d_in[0];
    const float* emb  = (const float*)d_in[1];
    const float* pos  = (const float*)d_in[2];
    const float* Wq   = (const float*)d_in[3];
    const float* bq   = (const float*)d_in[4];
    const float* Wk   = (const float*)d_in[5];
    const float* bk   = (const float*)d_in[6];
    const float* Wv   = (const float*)d_in[7];
    const float* bv   = (const float*)d_in[8];
    const float* Wf   = (const float*)d_in[9];
    const float* bf   = (const float*)d_in[10];
    const float* Wo   = (const float*)d_in[11];
    const float* bo   = (const float*)d_in[12];
    const float* lng  = (const float*)d_in[13];
    const float* lnb  = (const float*)d_in[14];
    const float* W1   = (const float*)d_in[15];
    const float* b1   = (const float*)d_in[16];
    const float* W2   = (const float*)d_in[17];
    const float* b2   = (const float*)d_in[18];
    const float* Wh1  = (const float*)d_in[19];
    const float* bh1  = (const float*)d_in[20];
    const float* Wh2  = (const float*)d_in[21];
    const float* bh2  = (const float*)d_in[22];
    float* out = (float*)d_out;

    float *ph, *pq, *pk, *pv, *pa, *ppq, *ppk, *pmlp, *pkv, *pz;
    cudaGetSymbolAddress((void**)&ph,   g_h);
    cudaGetSymbolAddress((void**)&pq,   g_q);
    cudaGetSymbolAddress((void**)&pk,   g_k);
    cudaGetSymbolAddress((void**)&pv,   g_v);
    cudaGetSymbolAddress((void**)&pa,   g_a);
    cudaGetSymbolAddress((void**)&ppq,  g_pq);
    cudaGetSymbolAddress((void**)&ppk,  g_pk);
    cudaGetSymbolAddress((void**)&pmlp, g_mlp);
    cudaGetSymbolAddress((void**)&pkv,  g_kv);
    cudaGetSymbolAddress((void**)&pz,   g_z);

    embed_kernel<<<CBS, 128>>>(x, emb, pos);

    for (int l = 0; l < CL; l++) {
        const float* wq = Wq + (long)l * CD * CD;
        const float* wk = Wk + (long)l * CD * CD;
        const float* wv = Wv + (long)l * CD * CD;
        const float* wf = Wf + (long)l * CD * CP;
        const float* wo = Wo + (long)l * CD * CD;
        const float* w1 = W1 + (long)l * CD * CDF;
        const float* w2 = W2 + (long)l * CDF * CD;
        const float* biq = bq + (long)l * CD;
        const float* bik = bk + (long)l * CD;
        const float* biv = bv + (long)l * CD;
        const float* bif = bf + (long)l * CP;
        const float* bio = bo + (long)l * CD;
        const float* bi1 = b1 + (long)l * CDF;
        const float* bi2 = b2 + (long)l * CD;

        dim3 gQKV(CD / 128, CBS / 128, 1);
        sgemm_nn<0><<<gQKV, 256>>>(ph, wq, biq, pq, CBS, CD, CD, 0, 0, 0, nullptr);
        sgemm_nn<0><<<gQKV, 256>>>(ph, wk, bik, pk, CBS, CD, CD, 0, 0, 0, nullptr);
        sgemm_nn<0><<<gQKV, 256>>>(ph, wv, biv, pv, CBS, CD, CD, 0, 0, 0, nullptr);

        dim3 gF(CP / 128, CBS / 128, 1);
        sgemm_nn<1><<<gF, 256>>>(pq, wf, bif, ppq, CBS, CP, CD, 0, 0, 0, nullptr);
        sgemm_nn<1><<<gF, 256>>>(pk, wf, bif, ppk, CBS, CP, CD, 0, 0, 0, nullptr);

        pksum_part_kernel<<<dim3(CB, PKCH), 128>>>();
        pksum_reduce_kernel<<<(CB * CP + 255) / 256, 256>>>();

        sgemm_tn_split<<<dim3(CD / 128, 1, CB * KVSPLIT), 256>>>();
        kv_reduce_kernel<<<(CB * CP * CD + 255) / 256, 256>>>();

        z_kernel<<<CBS / 8, 256>>>();

        // out[b,s,d] = (pq @ kv) / (z + eps)   (batched)
        dim3 gO(CD / 128, CS / 128, CB);
        sgemm_nn<3><<<gO, 256>>>(ppq, pkv, nullptr, pa,
                                 CS, CD, CP,
                                 (long)CS * CP, (long)CP * CD, (long)CS * CD, pz);

        sgemm_nn<0><<<gQKV, 256>>>(pa, wo, bio, pq, CBS, CD, CD, 0, 0, 0, nullptr);

        ln_kernel<<<CBS, 128>>>(pq, lng + (long)l * CD, lnb + (long)l * CD);

        dim3 g1(CDF / 128, CBS / 128, 1);
        sgemm_nn<2><<<g1, 256>>>(pq, w1, bi1, pmlp, CBS, CDF, CD, 0, 0, 0, nullptr);

        dim3 g2(CD / 128, CBS / 128, 1);
        sgemm_nn<0><<<g2, 256>>>(pmlp, w2, bi2, ph, CBS, CD, CDF, 0, 0, 0, nullptr);
    }

    pool_part_kernel<<<dim3(CB, POOLCH), CD>>>();
    pool_reduce_kernel<<<(CB * CD + 255) / 256, 256>>>();
    head1_kernel<<<CB, CDH>>>(Wh1, bh1);
    head2_kernel<<<1, 32>>>(Wh2, bh2, out);
}

// round 13
// speedup vs baseline: 1.1376x; 1.1368x over previous
#include <cuda_runtime.h>
#include <cuda_bf16.h>
#include <math.h>
#include <stdint.h>

// Problem constants
#define CB   8
#define CS   4096
#define CD   512
#define CP   128
#define CL   4
#define CDF  2048
#define CDH  256
#define CC   2
#define CBS  (CB*CS)          // 32768 tokens

#define KVSPLIT 8
#define PKCH    32
#define POOLCH  16

// ---------------- scratch (device globals; no allocation allowed) ----------------
__device__ float g_h   [(size_t)CBS*CD];
__device__ float g_q   [(size_t)CBS*CD];
__device__ float g_k   [(size_t)CBS*CD];
__device__ float g_v   [(size_t)CBS*CD];
__device__ float g_a   [(size_t)CBS*CD];
__device__ float g_pq  [(size_t)CBS*CP];
__device__ float g_pk  [(size_t)CBS*CP];
__device__ float g_mlp [(size_t)CBS*CDF];
__device__ float g_kv  [(size_t)CB*CP*CD];
__device__ float g_kvp [(size_t)CB*KVSPLIT*CP*CD];
__device__ float g_pks [(size_t)CB*CP];
__device__ float g_pkp [(size_t)PKCH*CB*CP];
__device__ float g_z   [(size_t)CBS];
__device__ float g_pool[(size_t)CB*CD];
__device__ float g_poolp[(size_t)POOLCH*CB*CD];
__device__ float g_h1  [(size_t)CB*CDH];

// ---------------- embedding ----------------
__global__ void embed_kernel(const int* __restrict__ x,
                             const float* __restrict__ emb,
                             const float* __restrict__ pos)
{
    long row = blockIdx.x;                // 0..CBS-1
    int  s   = (int)(row & (CS - 1));
    int  tok = x[row];
    int  t   = threadIdx.x;               // 128 threads, float4 each
    float4 e = ((const float4*)(emb + (long)tok * CD))[t];
    float4 p = ((const float4*)(pos + (long)s   * CD))[t];
    ((float4*)(g_h + row * CD))[t] = make_float4(e.x+p.x, e.y+p.y, e.z+p.z, e.w+p.w);
}

// ---------------- 3xTF32 tensor-core GEMM (NN), 128x128x8, epilogues ----------------
// EPI: 0 = +bias ; 1 = elu(+bias)+1 ; 2 = tanh-gelu(+bias) ; 3 = /(z+1e-6), no bias
// Split precision: x = hi + lo (both tf32-representable); acc += al*bh + ah*bl + ah*bh

__device__ __forceinline__ uint32_t f2tf32(float x)
{
    uint32_t r;
    asm("cvt.rna.tf32.f32 %0, %1;" : "=r"(r) : "f"(x));
    return r;
}

__device__ __forceinline__ void split_tf32(float x, uint32_t& hi, uint32_t& lo)
{
    hi = f2tf32(x);
    lo = f2tf32(x - __uint_as_float(hi));
}

#define MMA_TF32(d, a, b) \
    asm volatile("mma.sync.aligned.m16n8k8.row.col.f32.tf32.tf32.f32 " \
                 "{%0,%1,%2,%3},{%4,%5,%6,%7},{%8,%9},{%0,%1,%2,%3};" \
                 : "+f"(d[0]), "+f"(d[1]), "+f"(d[2]), "+f"(d[3]) \
                 : "r"(a[0]), "r"(a[1]), "r"(a[2]), "r"(a[3]), \
                   "r"(b[0]), "r"(b[1]))

#define TLDA 132   // 128 + 4 pad

template<int EPI>
__global__ __launch_bounds__(256)
void tgemm_nn(const float* __restrict__ A, const float* __restrict__ W,
              const float* __restrict__ bias, float* __restrict__ Cc,
              int M, int N, int K,
              long sA, long sB, long sC,
              const float* __restrict__ zvec)
{
    const int bz = blockIdx.z;
    A  += (long)bz * sA;
    W  += (long)bz * sB;
    Cc += (long)bz * sC;

    // hi/lo planes, double buffered, k-tile = 8
    __shared__ uint32_t Ah[2][8][TLDA];
    __shared__ uint32_t Al[2][8][TLDA];
    __shared__ uint32_t Bh[2][8][TLDA];
    __shared__ uint32_t Bl[2][8][TLDA];

    const int tid  = threadIdx.x;
    const int lane = tid & 31;
    const int warp = tid >> 5;
    const int wm   = warp & 1;             // 0..1 -> M offset wm*64
    const int wn   = warp >> 1;            // 0..3 -> N offset wn*32
    const int gp   = lane >> 2;            // group id (0..7)
    const int tg   = lane & 3;             // thread-in-group (0..3)

    const int brow = blockIdx.y * 128;
    const int bcol = blockIdx.x * 128;

    // global-load mapping: A tile 128x8 (one float4/thread), B tile 8x128
    const int aR  = tid >> 1;              // 0..127
    const int aC4 = (tid & 1) << 2;        // 0 or 4
    const int bR  = tid >> 5;              // 0..7
    const int bC4 = (tid & 31) << 2;       // 0..124

    const float* Ap = A + (long)(brow + aR) * K + aC4;
    const float* Bp = W + (long)bR * N + bcol + bC4;

    float acc[4][4][4];
    #pragma unroll
    for (int mi = 0; mi < 4; mi++)
        #pragma unroll
        for (int ni = 0; ni < 4; ni++)
            #pragma unroll
            for (int r = 0; r < 4; r++) acc[mi][ni][r] = 0.f;

    const int kTiles = K >> 3;

    // preload tile 0
    {
        float4 a = *(const float4*)Ap;
        float4 b = *(const float4*)Bp;
        uint32_t h, l;
        split_tf32(a.x, h, l); Ah[0][aC4+0][aR] = h; Al[0][aC4+0][aR] = l;
        split_tf32(a.y, h, l); Ah[0][aC4+1][aR] = h; Al[0][aC4+1][aR] = l;
        split_tf32(a.z, h, l); Ah[0][aC4+2][aR] = h; Al[0][aC4+2][aR] = l;
        split_tf32(a.w, h, l); Ah[0][aC4+3][aR] = h; Al[0][aC4+3][aR] = l;
        uint4 uh, ul;
        split_tf32(b.x, uh.x, ul.x);
        split_tf32(b.y, uh.y, ul.y);
        split_tf32(b.z, uh.z, ul.z);
        split_tf32(b.w, uh.w, ul.w);
        *(uint4*)&Bh[0][bR][bC4] = uh;
        *(uint4*)&Bl[0][bR][bC4] = ul;
    }
    __syncthreads();

    for (int kt = 0; kt < kTiles; kt++) {
        const int buf = kt & 1;
        const bool has = (kt + 1 < kTiles);
        float4 a, b;
        if (has) {
            const long ka = (long)(kt + 1) * 8;
            a = *(const float4*)(Ap + ka);
            b = *(const float4*)(Bp + ka * N);
        }

        // fragment loads
        uint32_t afh[4][4], afl[4][4], bfh[4][2], bfl[4][2];
        #pragma unroll
        for (int mi = 0; mi < 4; mi++) {
            const int m = wm * 64 + mi * 16 + gp;
            afh[mi][0] = Ah[buf][tg    ][m];
            afh[mi][1] = Ah[buf][tg    ][m + 8];
            afh[mi][2] = Ah[buf][tg + 4][m];
            afh[mi][3] = Ah[buf][tg + 4][m + 8];
            afl[mi][0] = Al[buf][tg    ][m];
            afl[mi][1] = Al[buf][tg    ][m + 8];
            afl[mi][2] = Al[buf][tg + 4][m];
            afl[mi][3] = Al[buf][tg + 4][m + 8];
        }
        #pragma unroll
        for (int ni = 0; ni < 4; ni++) {
            const int n = wn * 32 + ni * 8 + gp;
            bfh[ni][0] = Bh[buf][tg    ][n];
            bfh[ni][1] = Bh[buf][tg + 4][n];
            bfl[ni][0] = Bl[buf][tg    ][n];
            bfl[ni][1] = Bl[buf][tg + 4][n];
        }
        #pragma unroll
        for (int mi = 0; mi < 4; mi++)
            #pragma unroll
            for (int ni = 0; ni < 4; ni++) {
                MMA_TF32(acc[mi][ni], afl[mi], bfh[ni]);
                MMA_TF32(acc[mi][ni], afh[mi], bfl[ni]);
                MMA_TF32(acc[mi][ni], afh[mi], bfh[ni]);
            }

        if (has) {
            const int nb = buf ^ 1;
            uint32_t h, l;
            split_tf32(a.x, h, l); Ah[nb][aC4+0][aR] = h; Al[nb][aC4+0][aR] = l;
            split_tf32(a.y, h, l); Ah[nb][aC4+1][aR] = h; Al[nb][aC4+1][aR] = l;
            split_tf32(a.z, h, l); Ah[nb][aC4+2][aR] = h; Al[nb][aC4+2][aR] = l;
            split_tf32(a.w, h, l); Ah[nb][aC4+3][aR] = h; Al[nb][aC4+3][aR] = l;
            uint4 uh, ul;
            split_tf32(b.x, uh.x, ul.x);
            split_tf32(b.y, uh.y, ul.y);
            split_tf32(b.z, uh.z, ul.z);
            split_tf32(b.w, uh.w, ul.w);
            *(uint4*)&Bh[nb][bR][bC4] = uh;
            *(uint4*)&Bl[nb][bR][bC4] = ul;
        }
        __syncthreads();
    }

    // ---------------- epilogue ----------------
    float zr0[4], zr1[4];
    if (EPI == 3) {
        #pragma unroll
        for (int mi = 0; mi < 4; mi++) {
            const int r = brow + wm * 64 + mi * 16 + gp;
            zr0[mi] = 1.f / (zvec[(long)bz * CS + r    ] + 1e-6f);
            zr1[mi] = 1.f / (zvec[(long)bz * CS + r + 8] + 1e-6f);
        }
    }

    #pragma unroll
    for (int ni = 0; ni < 4; ni++) {
        const int c = bcol + wn * 32 + ni * 8 + 2 * tg;
        float bv0 = 0.f, bv1 = 0.f;
        if (EPI != 3) { bv0 = bias[c]; bv1 = bias[c + 1]; }
        #pragma unroll
        for (int mi = 0; mi < 4; mi++) {
            const int r0 = brow + wm * 64 + mi * 16 + gp;
            float v[4];
            v[0] = acc[mi][ni][0] + bv0;
            v[1] = acc[mi][ni][1] + bv1;
            v[2] = acc[mi][ni][2] + bv0;
            v[3] = acc[mi][ni][3] + bv1;
            #pragma unroll
            for (int r = 0; r < 4; r++) {
                float x = v[r];
                if (EPI == 1) {
                    x = (x > 0.f) ? (x + 1.f) : expf(x);
                } else if (EPI == 2) {
                    float u = 0.7978845608028654f * (x + 0.044715f * x * x * x);
                    x = 0.5f * x * (1.f + tanhf(u));
                } else if (EPI == 3) {
                    x = x * ((r < 2) ? zr0[mi] : zr1[mi]);
                }
                v[r] = x;
            }
            *(float2*)(Cc + (long)r0 * N + c)       = make_float2(v[0], v[1]);
            *(float2*)(Cc + (long)(r0 + 8) * N + c) = make_float2(v[2], v[3]);
        }
    }
}

// ---------------- TN SGEMM for kv = pk^T @ v, deterministic split-K (fp32) ----------------
__global__ __launch_bounds__(256)
void sgemm_tn_split(void)
{
    const int bz    = blockIdx.z;          // b*KVSPLIT + split
    const int b     = bz / KVSPLIT;
    const int split = bz % KVSPLIT;
    const int kBeg  = split * (CS / KVSPLIT);

    const float* A  = g_pk + (long)b * CS * CP;   // [S][P]
    const float* Bm = g_v  + (long)b * CS * CD;   // [S][D]
    float*       Cc = g_kvp + (long)bz * CP * CD;

    const int tid  = threadIdx.x;
    const int bcol = blockIdx.x * 128;     // within D

    __shared__ float As[8][128];
    __shared__ float Bs[8][128];

    const int lRow = tid >> 5;             // k in tile (0..7)
    const int lCol = (tid & 31) << 2;

    const int mBase = (tid >> 4) << 3;
    const int nBase = (tid & 15) << 3;

    float acc[8][8];
    #pragma unroll
    for (int i = 0; i < 8; i++)
        #pragma unroll
        for (int j = 0; j < 8; j++) acc[i][j] = 0.f;

    for (int k0 = 0; k0 < CS / KVSPLIT; k0 += 8) {
        const long kk = kBeg + k0 + lRow;
        *(float4*)&As[lRow][lCol] = *(const float4*)(A  + kk * CP + lCol);
        *(float4*)&Bs[lRow][lCol] = *(const float4*)(Bm + kk * CD + bcol + lCol);
        __syncthreads();
        #pragma unroll
        for (int k = 0; k < 8; k++) {
            float4 a0 = *(const float4*)&As[k][mBase];
            float4 a1 = *(const float4*)&As[k][mBase+4];
            float4 b0 = *(const float4*)&Bs[k][nBase];
            float4 b1 = *(const float4*)&Bs[k][nBase+4];
            float ra[8] = {a0.x,a0.y,a0.z,a0.w,a1.x,a1.y,a1.z,a1.w};
            float rb[8] = {b0.x,b0.y,b0.z,b0.w,b1.x,b1.y,b1.z,b1.w};
            #pragma unroll
            for (int i = 0; i < 8; i++)
                #pragma unroll
                for (int j = 0; j < 8; j++)
                    acc[i][j] = fmaf(ra[i], rb[j], acc[i][j]);
        }
        __syncthreads();
    }

    #pragma unroll
    for (int i = 0; i < 8; i++) {
        float4* cp = (float4*)(Cc + (long)(mBase + i) * CD + bcol + nBase);
        cp[0] = make_float4(acc[i][0], acc[i][1], acc[i][2], acc[i][3]);
        cp[1] = make_float4(acc[i][4], acc[i][5], acc[i][6], acc[i][7]);
    }
}

__global__ void kv_reduce_kernel(void)
{
    long idx = (long)blockIdx.x * blockDim.x + threadIdx.x;   // over CB*CP*CD
    if (idx >= (long)CB * CP * CD) return;
    long b = idx / (CP * CD);
    long r = idx % (CP * CD);
    float s = 0.f;
    #pragma unroll
    for (int sp = 0; sp < KVSPLIT; sp++)
        s += g_kvp[(b * KVSPLIT + sp) * (long)(CP * CD) + r];
    g_kv[idx] = s;
}

// ---------------- pk.sum over S ----------------
__global__ void pksum_part_kernel(void)   // grid (CB, PKCH), block 128
{
    int b = blockIdx.x, ch = blockIdx.y, t = threadIdx.x;
    const int chunk = CS / PKCH;
    float acc = 0.f;
    const float* p = g_pk + ((long)b * CS + (long)ch * chunk) * CP + t;
    for (int s = 0; s < chunk; s++) acc += p[(long)s * CP];
    g_pkp[((long)ch * CB + b) * CP + t] = acc;
}

__global__ void pksum_reduce_kernel(void)
{
    int idx = blockIdx.x * blockDim.x + threadIdx.x;
    if (idx >= CB * CP) return;
    float s = 0.f;
    #pragma unroll
    for (int ch = 0; ch < PKCH; ch++)
        s += g_pkp[(long)ch * CB * CP + idx];
    g_pks[idx] = s;
}

// ---------------- z = pq . pksum (per row) ----------------
__global__ void z_kernel(void)   // grid CBS/8, block 256 (8 warps)
{
    const long row  = (long)blockIdx.x * 8 + (threadIdx.x >> 5);
    const int  lane = threadIdx.x & 31;
    const int  b    = (int)(row / CS);
    const float* pr = g_pq  + row * CP;
    const float* ps = g_pks + (long)b * CP;
    float acc = 0.f;
    #pragma unroll
    for (int i = lane; i < CP; i += 32) acc += pr[i] * ps[i];
    #pragma unroll
    for (int o = 16; o; o >>= 1) acc += __shfl_xor_sync(0xffffffffu, acc, o);
    if (lane == 0) g_z[row] = acc;
}

// ---------------- layernorm, in-place, one 128-thread block per row ----------------
__global__ void ln_kernel(float* __restrict__ X,
                          const float* __restrict__ gamma,
                          const float* __restrict__ beta)
{
    __shared__ float red[128];
    const long row = blockIdx.x;
    float4* xp = (float4*)(X + row * CD);
    const int t = threadIdx.x;
    float4 v = xp[t];

    red[t] = v.x + v.y + v.z + v.w;
    __syncthreads();
    for (int o = 64; o; o >>= 1) { if (t < o) red[t] += red[t + o]; __syncthreads(); }
    const float mu = red[0] * (1.f / CD);
    __syncthreads();

    float dx = v.x - mu, dy = v.y - mu, dz = v.z - mu, dw = v.w - mu;
    red[t] = dx*dx + dy*dy + dz*dz + dw*dw;
    __syncthreads();
    for (int o = 64; o; o >>= 1) { if (t < o) red[t] += red[t + o]; __syncthreads(); }
    const float rstd = rsqrtf(red[0] * (1.f / CD) + 1e-5f);

    const float4 g4 = ((const float4*)gamma)[t];
    const float4 b4 = ((const float4*)beta)[t];
    float4 o;
    o.x = dx * rstd * g4.x + b4.x;
    o.y = dy * rstd * g4.y + b4.y;
    o.z = dz * rstd * g4.z + b4.z;
    o.w = dw * rstd * g4.w + b4.w;
    xp[t] = o;
}

// ---------------- mean pool over S ----------------
__global__ void pool_part_kernel(void)    // grid (CB, POOLCH), block CD
{
    int b = blockIdx.x, ch = blockIdx.y, d = threadIdx.x;
    const int chunk = CS / POOLCH;
    float acc = 0.f;
    const float* p = g_h + ((long)b * CS + (long)ch * chunk) * CD + d;
    for (int s = 0; s < chunk; s++) acc += p[(long)s * CD];
    g_poolp[((long)ch * CB + b) * CD + d] = acc;
}

__global__ void pool_reduce_kernel(void)
{
    int idx = blockIdx.x * blockDim.x + threadIdx.x;
    if (idx >= CB * CD) return;
    float s = 0.f;
    #pragma unroll
    for (int ch = 0; ch < POOLCH; ch++)
        s += g_poolp[(long)ch * CB * CD + idx];
    g_pool[idx] = s * (1.f / CS);
}

// ---------------- head ----------------
__global__ void head1_kernel(const float* __restrict__ Wh1,
                             const float* __restrict__ bh1)
{
    int b = blockIdx.x, t = threadIdx.x;       // block = CDH threads
    const float* pr = g_pool + (long)b * CD;
    float acc = 0.f;
    for (int k = 0; k < CD; k++)
        acc = fmaf(pr[k], Wh1[(long)k * CDH + t], acc);
    float v = acc + bh1[t];
    g_h1[(long)b * CDH + t] = v > 0.f ? v : 0.f;
}

__global__ void head2_kernel(const float* __restrict__ Wh2,
                             const float* __restrict__ bh2,
                             float* __restrict__ out)
{
    int idx = threadIdx.x;
    if (idx >= CB * CC) return;
    int b = idx / CC, c = idx % CC;
    const float* h1 = g_h1 + (long)b * CDH;
    float acc = 0.f;
    for (int k = 0; k < CDH; k++)
        acc = fmaf(h1[k], Wh2[(long)k * CC + c], acc);
    out[idx] = acc + bh2[c];
}

// ---------------- host ----------------
extern "C" void kernel_launch(void* const* d_in, const int* in_sizes, int n_in,
                              void* d_out, int out_size)
{
    (void)in_sizes; (void)n_in; (void)out_size;

    const int*   x    = (const int*)  d_in[0];
    const float* emb  = (const float*)d_in[1];
    const float* pos  = (const float*)d_in[2];
    const float* Wq   = (const float*)d_in[3];
    const float* bq   = (const float*)d_in[4];
    const float* Wk   = (const float*)d_in[5];
    const float* bk   = (const float*)d_in[6];
    const float* Wv   = (const float*)d_in[7];
    const float* bv   = (const float*)d_in[8];
    const float* Wf   = (const float*)d_in[9];
    const float* bf   = (const float*)d_in[10];
    const float* Wo   = (const float*)d_in[11];
    const float* bo   = (const float*)d_in[12];
    const float* lng  = (const float*)d_in[13];
    const float* lnb  = (const float*)d_in[14];
    const float* W1   = (const float*)d_in[15];
    const float* b1   = (const float*)d_in[16];
    const float* W2   = (const float*)d_in[17];
    const float* b2   = (const float*)d_in[18];
    const float* Wh1  = (const float*)d_in[19];
    const float* bh1  = (const float*)d_in[20];
    const float* Wh2  = (const float*)d_in[21];
    const float* bh2  = (const float*)d_in[22];
    float* out = (float*)d_out;

    float *ph, *pq, *pk, *pv, *pa, *ppq, *ppk, *pmlp, *pkv, *pz;
    cudaGetSymbolAddress((void**)&ph,   g_h);
    cudaGetSymbolAddress((void**)&pq,   g_q);
    cudaGetSymbolAddress((void**)&pk,   g_k);
    cudaGetSymbolAddress((void**)&pv,   g_v);
    cudaGetSymbolAddress((void**)&pa,   g_a);
    cudaGetSymbolAddress((void**)&ppq,  g_pq);
    cudaGetSymbolAddress((void**)&ppk,  g_pk);
    cudaGetSymbolAddress((void**)&pmlp, g_mlp);
    cudaGetSymbolAddress((void**)&pkv,  g_kv);
    cudaGetSymbolAddress((void**)&pz,   g_z);

    embed_kernel<<<CBS, 128>>>(x, emb, pos);

    for (int l = 0; l < CL; l++) {
        const float* wq = Wq + (long)l * CD * CD;
        const float* wk = Wk + (long)l * CD * CD;
        const float* wv = Wv + (long)l * CD * CD;
        const float* wf = Wf + (long)l * CD * CP;
        const float* wo = Wo + (long)l * CD * CD;
        const float* w1 = W1 + (long)l * CD * CDF;
        const float* w2 = W2 + (long)l * CDF * CD;
        const float* biq = bq + (long)l * CD;
        const float* bik = bk + (long)l * CD;
        const float* biv = bv + (long)l * CD;
        const float* bif = bf + (long)l * CP;
        const float* bio = bo + (long)l * CD;
        const float* bi1 = b1 + (long)l * CDF;
        const float* bi2 = b2 + (long)l * CD;

        dim3 gQKV(CD / 128, CBS / 128, 1);
        tgemm_nn<0><<<gQKV, 256>>>(ph, wq, biq, pq, CBS, CD, CD, 0, 0, 0, nullptr);
        tgemm_nn<0><<<gQKV, 256>>>(ph, wk, bik, pk, CBS, CD, CD, 0, 0, 0, nullptr);
        tgemm_nn<0><<<gQKV, 256>>>(ph, wv, biv, pv, CBS, CD, CD, 0, 0, 0, nullptr);

        dim3 gF(CP / 128, CBS / 128, 1);
        tgemm_nn<1><<<gF, 256>>>(pq, wf, bif, ppq, CBS, CP, CD, 0, 0, 0, nullptr);
        tgemm_nn<1><<<gF, 256>>>(pk, wf, bif, ppk, CBS, CP, CD, 0, 0, 0, nullptr);

        pksum_part_kernel<<<dim3(CB, PKCH), 128>>>();
        pksum_reduce_kernel<<<(CB * CP + 255) / 256, 256>>>();

        sgemm_tn_split<<<dim3(CD / 128, 1, CB * KVSPLIT), 256>>>();
        kv_reduce_kernel<<<(CB * CP * CD + 255) / 256, 256>>>();

        z_kernel<<<CBS / 8, 256>>>();

        // out[b,s,d] = (pq @ kv) / (z + eps)   (batched)
        dim3 gO(CD / 128, CS / 128, CB);
        tgemm_nn<3><<<gO, 256>>>(ppq, pkv, nullptr, pa,
                                 CS, CD, CP,
                                 (long)CS * CP, (long)CP * CD, (long)CS * CD, pz);

        tgemm_nn<0><<<gQKV, 256>>>(pa, wo, bio, pq, CBS, CD, CD, 0, 0, 0, nullptr);

        ln_kernel<<<CBS, 128>>>(pq, lng + (long)l * CD, lnb + (long)l * CD);

        dim3 g1(CDF / 128, CBS / 128, 1);
        tgemm_nn<2><<<g1, 256>>>(pq, w1, bi1, pmlp, CBS, CDF, CD, 0, 0, 0, nullptr);

        dim3 g2(CD / 128, CBS / 128, 1);
        tgemm_nn<0><<<g2, 256>>>(pmlp, w2, bi2, ph, CBS, CD, CDF, 0, 0, 0, nullptr);
    }

    pool_part_kernel<<<dim3(CB, POOLCH), CD>>>();
    pool_reduce_kernel<<<(CB * CD + 255) / 256, 256>>>();
    head1_kernel<<<CB, CDH>>>(Wh1, bh1);
    head2_kernel<<<1, 32>>>(Wh2, bh2, out);
}

// round 14
// speedup vs baseline: 2.5949x; 2.2809x over previous
#include <cuda_runtime.h>
#include <cuda_bf16.h>
#include <math.h>
#include <stdint.h>

// Problem constants
#define CB   8
#define CS   4096
#define CD   512
#define CP   128
#define CL   4
#define CDF  2048
#define CDH  256
#define CC   2
#define CBS  (CB*CS)          // 32768 tokens

#define KVSPLIT 8
#define PKCH    32
#define POOLCH  16

// ---------------- scratch (device globals; no allocation allowed) ----------------
__device__ float g_h   [(size_t)CBS*CD];
__device__ float g_q   [(size_t)CBS*CD];
__device__ float g_k   [(size_t)CBS*CD];
__device__ float g_v   [(size_t)CBS*CD];
__device__ float g_a   [(size_t)CBS*CD];
__device__ float g_pq  [(size_t)CBS*CP];
__device__ float g_pk  [(size_t)CBS*CP];
__device__ float g_mlp [(size_t)CBS*CDF];
__device__ float g_kv  [(size_t)CB*CP*CD];
__device__ float g_kvp [(size_t)CB*KVSPLIT*CP*CD];
__device__ float g_pks [(size_t)CB*CP];
__device__ float g_pkp [(size_t)PKCH*CB*CP];
__device__ float g_z   [(size_t)CBS];
__device__ float g_pool[(size_t)CB*CD];
__device__ float g_poolp[(size_t)POOLCH*CB*CD];
__device__ float g_h1  [(size_t)CB*CDH];

// ---------------- embedding ----------------
__global__ void embed_kernel(const int* __restrict__ x,
                             const float* __restrict__ emb,
                             const float* __restrict__ pos)
{
    long row = blockIdx.x;                // 0..CBS-1
    int  s   = (int)(row & (CS - 1));
    int  tok = x[row];
    int  t   = threadIdx.x;               // 128 threads, float4 each
    float4 e = ((const float4*)(emb + (long)tok * CD))[t];
    float4 p = ((const float4*)(pos + (long)s   * CD))[t];
    ((float4*)(g_h + row * CD))[t] = make_float4(e.x+p.x, e.y+p.y, e.z+p.z, e.w+p.w);
}

// ---------------- 3xBF16 tensor-core GEMM (NN), 128x128x16, ldmatrix ----------------
// EPI: 0 = +bias ; 1 = elu(+bias)+1 ; 2 = tanh-gelu(+bias) ; 3 = /(z+1e-6), no bias
// Split precision: x = hi + lo (bf16 each); acc += al*bh + ah*bl + ah*bh
// (omitted al*bl ~ 2^-18 relative -> well under the 1e-3 gate)

#define MMA_BF16(d, a, b) \
    asm volatile("mma.sync.aligned.m16n8k16.row.col.f32.bf16.bf16.f32 " \
                 "{%0,%1,%2,%3},{%4,%5,%6,%7},{%8,%9},{%0,%1,%2,%3};" \
                 : "+f"(d[0]), "+f"(d[1]), "+f"(d[2]), "+f"(d[3]) \
                 : "r"(a[0]), "r"(a[1]), "r"(a[2]), "r"(a[3]), \
                   "r"(b[0]), "r"(b[1]))

#define LDSM4(r0,r1,r2,r3,addr) \
    asm volatile("ldmatrix.sync.aligned.m8n8.x4.shared.b16 {%0,%1,%2,%3},[%4];" \
                 : "=r"(r0), "=r"(r1), "=r"(r2), "=r"(r3) : "r"(addr))

#define LDSM2T(r0,r1,addr) \
    asm volatile("ldmatrix.sync.aligned.m8n8.x2.trans.shared.b16 {%0,%1},[%2];" \
                 : "=r"(r0), "=r"(r1) : "r"(addr))

#define ASTR 24    // bf16 units per A smem row (16 + 8 pad) -> conflict-free ldmatrix
#define BSTR 136   // bf16 units per B smem row (128 + 8 pad)

// split 4 floats into packed-bf16 hi pair-words and lo pair-words
__device__ __forceinline__ void split4(float x0, float x1, float x2, float x3,
                                       uint32_t& h01, uint32_t& h23,
                                       uint32_t& l01, uint32_t& l23)
{
    __nv_bfloat162 h;
    h = __floats2bfloat162_rn(x0, x1); h01 = *(uint32_t*)&h;
    float r0 = x0 - __bfloat162float(h.x);
    float r1 = x1 - __bfloat162float(h.y);
    __nv_bfloat162 l = __floats2bfloat162_rn(r0, r1); l01 = *(uint32_t*)&l;
    h = __floats2bfloat162_rn(x2, x3); h23 = *(uint32_t*)&h;
    float r2 = x2 - __bfloat162float(h.x);
    float r3 = x3 - __bfloat162float(h.y);
    l = __floats2bfloat162_rn(r2, r3); l23 = *(uint32_t*)&l;
}

template<int EPI>
__global__ __launch_bounds__(256, 2)
void tgemm_nn(const float* __restrict__ A, const float* __restrict__ W,
              const float* __restrict__ bias, float* __restrict__ Cc,
              int M, int N, int K,
              long sA, long sB, long sC,
              const float* __restrict__ zvec)
{
    const int bz = blockIdx.z;
    A  += (long)bz * sA;
    W  += (long)bz * sB;
    Cc += (long)bz * sC;

    __shared__ __align__(16) uint16_t Ah[2][128*ASTR];
    __shared__ __align__(16) uint16_t Al[2][128*ASTR];
    __shared__ __align__(16) uint16_t Bh[2][16*BSTR];
    __shared__ __align__(16) uint16_t Bl[2][16*BSTR];

    const int tid  = threadIdx.x;
    const int lane = tid & 31;
    const int warp = tid >> 5;
    const int wm   = warp & 1;             // M offset wm*64
    const int wn   = warp >> 1;            // N offset wn*32
    const int gp   = lane >> 2;
    const int tg   = lane & 3;

    const int brow = blockIdx.y * 128;
    const int bcol = blockIdx.x * 128;

    // global-load mapping: A tile 128x16 (2 float4/thread), B tile 16x128 (2 float4/thread)
    const int aR  = tid >> 1;              // 0..127
    const int aK8 = (tid & 1) << 3;        // 0 or 8
    const int bK  = tid >> 5;              // 0..7 (rows bK and bK+8)
    const int bC4 = lane << 2;             // 0..124

    const float* Ap  = A + (long)(brow + aR) * K + aK8;
    const float* Bp0 = W + (long)bK * N + bcol + bC4;
    const float* Bp1 = Bp0 + 8 * (long)N;

    // smem byte bases
    const uint32_t ahB = (uint32_t)__cvta_generic_to_shared(&Ah[0][0]);
    const uint32_t alB = (uint32_t)__cvta_generic_to_shared(&Al[0][0]);
    const uint32_t bhB = (uint32_t)__cvta_generic_to_shared(&Bh[0][0]);
    const uint32_t blB = (uint32_t)__cvta_generic_to_shared(&Bl[0][0]);
    const uint32_t ABUF = 128u * ASTR * 2u;
    const uint32_t BBUF = 16u * BSTR * 2u;

    // ldmatrix lane addressing
    const int aldR = lane & 15;
    const int aldK = (lane & 16) ? 8 : 0;
    const int bldK = lane & 15;

    float acc[4][4][4];
    #pragma unroll
    for (int mi = 0; mi < 4; mi++)
        #pragma unroll
        for (int ni = 0; ni < 4; ni++)
            #pragma unroll
            for (int r = 0; r < 4; r++) acc[mi][ni][r] = 0.f;

    const int kTiles = K >> 4;

    // ---- stage tile 0 ----
    {
        float4 a0 = *(const float4*)Ap;
        float4 a1 = *(const float4*)(Ap + 4);
        float4 b0 = *(const float4*)Bp0;
        float4 b1 = *(const float4*)Bp1;
        uint4 uh, ul;
        split4(a0.x, a0.y, a0.z, a0.w, uh.x, uh.y, ul.x, ul.y);
        split4(a1.x, a1.y, a1.z, a1.w, uh.z, uh.w, ul.z, ul.w);
        *(uint4*)&Ah[0][aR*ASTR + aK8] = uh;
        *(uint4*)&Al[0][aR*ASTR + aK8] = ul;
        uint2 vh, vl;
        split4(b0.x, b0.y, b0.z, b0.w, vh.x, vh.y, vl.x, vl.y);
        *(uint2*)&Bh[0][bK*BSTR + bC4] = vh;
        *(uint2*)&Bl[0][bK*BSTR + bC4] = vl;
        split4(b1.x, b1.y, b1.z, b1.w, vh.x, vh.y, vl.x, vl.y);
        *(uint2*)&Bh[0][(bK+8)*BSTR + bC4] = vh;
        *(uint2*)&Bl[0][(bK+8)*BSTR + bC4] = vl;
    }
    __syncthreads();

    for (int kt = 0; kt < kTiles; kt++) {
        const int buf = kt & 1;
        const bool has = (kt + 1 < kTiles);
        float4 a0, a1, b0, b1;
        if (has) {
            const long ka = (long)(kt + 1) * 16;
            a0 = *(const float4*)(Ap + ka);
            a1 = *(const float4*)(Ap + ka + 4);
            b0 = *(const float4*)(Bp0 + ka * N);
            b1 = *(const float4*)(Bp1 + ka * N);
        }

        // B fragments (all ni, hi+lo)
        uint32_t bfh[4][2], bfl[4][2];
        #pragma unroll
        for (int ni = 0; ni < 4; ni++) {
            const uint32_t off = (uint32_t)((bldK*BSTR + wn*32 + ni*8) * 2);
            LDSM2T(bfh[ni][0], bfh[ni][1], bhB + buf*BBUF + off);
            LDSM2T(bfl[ni][0], bfl[ni][1], blB + buf*BBUF + off);
        }

        // A fragments per mi, then MMAs
        #pragma unroll
        for (int mi = 0; mi < 4; mi++) {
            const uint32_t off = (uint32_t)(((wm*64 + mi*16 + aldR)*ASTR + aldK) * 2);
            uint32_t afh[4], afl[4];
            LDSM4(afh[0], afh[1], afh[2], afh[3], ahB + buf*ABUF + off);
            LDSM4(afl[0], afl[1], afl[2], afl[3], alB + buf*ABUF + off);
            #pragma unroll
            for (int ni = 0; ni < 4; ni++) {
                MMA_BF16(acc[mi][ni], afl, bfh[ni]);
                MMA_BF16(acc[mi][ni], afh, bfl[ni]);
                MMA_BF16(acc[mi][ni], afh, bfh[ni]);
            }
        }

        if (has) {
            const int nb = buf ^ 1;
            uint4 uh, ul;
            split4(a0.x, a0.y, a0.z, a0.w, uh.x, uh.y, ul.x, ul.y);
            split4(a1.x, a1.y, a1.z, a1.w, uh.z, uh.w, ul.z, ul.w);
            *(uint4*)&Ah[nb][aR*ASTR + aK8] = uh;
            *(uint4*)&Al[nb][aR*ASTR + aK8] = ul;
            uint2 vh, vl;
            split4(b0.x, b0.y, b0.z, b0.w, vh.x, vh.y, vl.x, vl.y);
            *(uint2*)&Bh[nb][bK*BSTR + bC4] = vh;
            *(uint2*)&Bl[nb][bK*BSTR + bC4] = vl;
            split4(b1.x, b1.y, b1.z, b1.w, vh.x, vh.y, vl.x, vl.y);
            *(uint2*)&Bh[nb][(bK+8)*BSTR + bC4] = vh;
            *(uint2*)&Bl[nb][(bK+8)*BSTR + bC4] = vl;
        }
        __syncthreads();
    }

    // ---------------- epilogue ----------------
    float zr0[4], zr1[4];
    if (EPI == 3) {
        #pragma unroll
        for (int mi = 0; mi < 4; mi++) {
            const int r = brow + wm * 64 + mi * 16 + gp;
            zr0[mi] = 1.f / (zvec[(long)bz * CS + r    ] + 1e-6f);
            zr1[mi] = 1.f / (zvec[(long)bz * CS + r + 8] + 1e-6f);
        }
    }

    #pragma unroll
    for (int ni = 0; ni < 4; ni++) {
        const int c = bcol + wn * 32 + ni * 8 + 2 * tg;
        float bv0 = 0.f, bv1 = 0.f;
        if (EPI != 3) { bv0 = bias[c]; bv1 = bias[c + 1]; }
        #pragma unroll
        for (int mi = 0; mi < 4; mi++) {
            const int r0 = brow + wm * 64 + mi * 16 + gp;
            float v[4];
            v[0] = acc[mi][ni][0] + bv0;
            v[1] = acc[mi][ni][1] + bv1;
            v[2] = acc[mi][ni][2] + bv0;
            v[3] = acc[mi][ni][3] + bv1;
            #pragma unroll
            for (int r = 0; r < 4; r++) {
                float x = v[r];
                if (EPI == 1) {
                    x = (x > 0.f) ? (x + 1.f) : expf(x);
                } else if (EPI == 2) {
                    float u = 0.7978845608028654f * (x + 0.044715f * x * x * x);
                    x = 0.5f * x * (1.f + tanhf(u));
                } else if (EPI == 3) {
                    x = x * ((r < 2) ? zr0[mi] : zr1[mi]);
                }
                v[r] = x;
            }
            *(float2*)(Cc + (long)r0 * N + c)       = make_float2(v[0], v[1]);
            *(float2*)(Cc + (long)(r0 + 8) * N + c) = make_float2(v[2], v[3]);
        }
    }
}

// ---------------- TN SGEMM for kv = pk^T @ v, deterministic split-K (fp32) ----------------
__global__ __launch_bounds__(256)
void sgemm_tn_split(void)
{
    const int bz    = blockIdx.z;          // b*KVSPLIT + split
    const int b     = bz / KVSPLIT;
    const int split = bz % KVSPLIT;
    const int kBeg  = split * (CS / KVSPLIT);

    const float* A  = g_pk + (long)b * CS * CP;   // [S][P]
    const float* Bm = g_v  + (long)b * CS * CD;   // [S][D]
    float*       Cc = g_kvp + (long)bz * CP * CD;

    const int tid  = threadIdx.x;
    const int bcol = blockIdx.x * 128;     // within D

    __shared__ float As[8][128];
    __shared__ float Bs[8][128];

    const int lRow = tid >> 5;             // k in tile (0..7)
    const int lCol = (tid & 31) << 2;

    const int mBase = (tid >> 4) << 3;
    const int nBase = (tid & 15) << 3;

    float acc[8][8];
    #pragma unroll
    for (int i = 0; i < 8; i++)
        #pragma unroll
        for (int j = 0; j < 8; j++) acc[i][j] = 0.f;

    for (int k0 = 0; k0 < CS / KVSPLIT; k0 += 8) {
        const long kk = kBeg + k0 + lRow;
        *(float4*)&As[lRow][lCol] = *(const float4*)(A  + kk * CP + lCol);
        *(float4*)&Bs[lRow][lCol] = *(const float4*)(Bm + kk * CD + bcol + lCol);
        __syncthreads();
        #pragma unroll
        for (int k = 0; k < 8; k++) {
            float4 a0 = *(const float4*)&As[k][mBase];
            float4 a1 = *(const float4*)&As[k][mBase+4];
            float4 b0 = *(const float4*)&Bs[k][nBase];
            float4 b1 = *(const float4*)&Bs[k][nBase+4];
            float ra[8] = {a0.x,a0.y,a0.z,a0.w,a1.x,a1.y,a1.z,a1.w};
            float rb[8] = {b0.x,b0.y,b0.z,b0.w,b1.x,b1.y,b1.z,b1.w};
            #pragma unroll
            for (int i = 0; i < 8; i++)
                #pragma unroll
                for (int j = 0; j < 8; j++)
                    acc[i][j] = fmaf(ra[i], rb[j], acc[i][j]);
        }
        __syncthreads();
    }

    #pragma unroll
    for (int i = 0; i < 8; i++) {
        float4* cp = (float4*)(Cc + (long)(mBase + i) * CD + bcol + nBase);
        cp[0] = make_float4(acc[i][0], acc[i][1], acc[i][2], acc[i][3]);
        cp[1] = make_float4(acc[i][4], acc[i][5], acc[i][6], acc[i][7]);
    }
}

__global__ void kv_reduce_kernel(void)
{
    long idx = (long)blockIdx.x * blockDim.x + threadIdx.x;   // over CB*CP*CD
    if (idx >= (long)CB * CP * CD) return;
    long b = idx / (CP * CD);
    long r = idx % (CP * CD);
    float s = 0.f;
    #pragma unroll
    for (int sp = 0; sp < KVSPLIT; sp++)
        s += g_kvp[(b * KVSPLIT + sp) * (long)(CP * CD) + r];
    g_kv[idx] = s;
}

// ---------------- pk.sum over S ----------------
__global__ void pksum_part_kernel(void)   // grid (CB, PKCH), block 128
{
    int b = blockIdx.x, ch = blockIdx.y, t = threadIdx.x;
    const int chunk = CS / PKCH;
    float acc = 0.f;
    const float* p = g_pk + ((long)b * CS + (long)ch * chunk) * CP + t;
    for (int s = 0; s < chunk; s++) acc += p[(long)s * CP];
    g_pkp[((long)ch * CB + b) * CP + t] = acc;
}

__global__ void pksum_reduce_kernel(void)
{
    int idx = blockIdx.x * blockDim.x + threadIdx.x;
    if (idx >= CB * CP) return;
    float s = 0.f;
    #pragma unroll
    for (int ch = 0; ch < PKCH; ch++)
        s += g_pkp[(long)ch * CB * CP + idx];
    g_pks[idx] = s;
}

// ---------------- z = pq . pksum (per row) ----------------
__global__ void z_kernel(void)   // grid CBS/8, block 256 (8 warps)
{
    const long row  = (long)blockIdx.x * 8 + (threadIdx.x >> 5);
    const int  lane = threadIdx.x & 31;
    const int  b    = (int)(row / CS);
    const float* pr = g_pq  + row * CP;
    const float* ps = g_pks + (long)b * CP;
    float acc = 0.f;
    #pragma unroll
    for (int i = lane; i < CP; i += 32) acc += pr[i] * ps[i];
    #pragma unroll
    for (int o = 16; o; o >>= 1) acc += __shfl_xor_sync(0xffffffffu, acc, o);
    if (lane == 0) g_z[row] = acc;
}

// ---------------- layernorm, in-place, one 128-thread block per row ----------------
__global__ void ln_kernel(float* __restrict__ X,
                          const float* __restrict__ gamma,
                          const float* __restrict__ beta)
{
    __shared__ float red[128];
    const long row = blockIdx.x;
    float4* xp = (float4*)(X + row * CD);
    const int t = threadIdx.x;
    float4 v = xp[t];

    red[t] = v.x + v.y + v.z + v.w;
    __syncthreads();
    for (int o = 64; o; o >>= 1) { if (t < o) red[t] += red[t + o]; __syncthreads(); }
    const float mu = red[0] * (1.f / CD);
    __syncthreads();

    float dx = v.x - mu, dy = v.y - mu, dz = v.z - mu, dw = v.w - mu;
    red[t] = dx*dx + dy*dy + dz*dz + dw*dw;
    __syncthreads();
    for (int o = 64; o; o >>= 1) { if (t < o) red[t] += red[t + o]; __syncthreads(); }
    const float rstd = rsqrtf(red[0] * (1.f / CD) + 1e-5f);

    const float4 g4 = ((const float4*)gamma)[t];
    const float4 b4 = ((const float4*)beta)[t];
    float4 o;
    o.x = dx * rstd * g4.x + b4.x;
    o.y = dy * rstd * g4.y + b4.y;
    o.z = dz * rstd * g4.z + b4.z;
    o.w = dw * rstd * g4.w + b4.w;
    xp[t] = o;
}

// ---------------- mean pool over S ----------------
__global__ void pool_part_kernel(void)    // grid (CB, POOLCH), block CD
{
    int b = blockIdx.x, ch = blockIdx.y, d = threadIdx.x;
    const int chunk = CS / POOLCH;
    float acc = 0.f;
    const float* p = g_h + ((long)b * CS + (long)ch * chunk) * CD + d;
    for (int s = 0; s < chunk; s++) acc += p[(long)s * CD];
    g_poolp[((long)ch * CB + b) * CD + d] = acc;
}

__global__ void pool_reduce_kernel(void)
{
    int idx = blockIdx.x * blockDim.x + threadIdx.x;
    if (idx >= CB * CD) return;
    float s = 0.f;
    #pragma unroll
    for (int ch = 0; ch < POOLCH; ch++)
        s += g_poolp[(long)ch * CB * CD + idx];
    g_pool[idx] = s * (1.f / CS);
}

// ---------------- head ----------------
__global__ void head1_kernel(const float* __restrict__ Wh1,
                             const float* __restrict__ bh1)
{
    int b = blockIdx.x, t = threadIdx.x;       // block = CDH threads
    const float* pr = g_pool + (long)b * CD;
    float acc = 0.f;
    for (int k = 0; k < CD; k++)
        acc = fmaf(pr[k], Wh1[(long)k * CDH + t], acc);
    float v = acc + bh1[t];
    g_h1[(long)b * CDH + t] = v > 0.f ? v : 0.f;
}

__global__ void head2_kernel(const float* __restrict__ Wh2,
                             const float* __restrict__ bh2,
                             float* __restrict__ out)
{
    int idx = threadIdx.x;
    if (idx >= CB * CC) return;
    int b = idx / CC, c = idx % CC;
    const float* h1 = g_h1 + (long)b * CDH;
    float acc = 0.f;
    for (int k = 0; k < CDH; k++)
        acc = fmaf(h1[k], Wh2[(long)k * CC + c], acc);
    out[idx] = acc + bh2[c];
}

// ---------------- host ----------------
extern "C" void kernel_launch(void* const* d_in, const int* in_sizes, int n_in,
                              void* d_out, int out_size)
{
    (void)in_sizes; (void)n_in; (void)out_size;

    const int*   x    = (const int*)  d_in[0];
    const float* emb  = (const float*)d_in[1];
    const float* pos  = (const float*)d_in[2];
    const float* Wq   = (const float*)d_in[3];
    const float* bq   = (const float*)d_in[4];
    const float* Wk   = (const float*)d_in[5];
    const float* bk   = (const float*)d_in[6];
    const float* Wv   = (const float*)d_in[7];
    const float* bv   = (const float*)d_in[8];
    const float* Wf   = (const float*)d_in[9];
    const float* bf   = (const float*)d_in[10];
    const float* Wo   = (const float*)d_in[11];
    const float* bo   = (const float*)d_in[12];
    const float* lng  = (const float*)d_in[13];
    const float* lnb  = (const float*)d_in[14];
    const float* W1   = (const float*)d_in[15];
    const float* b1   = (const float*)d_in[16];
    const float* W2   = (const float*)d_in[17];
    const float* b2   = (const float*)d_in[18];
    const float* Wh1  = (const float*)d_in[19];
    const float* bh1  = (const float*)d_in[20];
    const float* Wh2  = (const float*)d_in[21];
    const float* bh2  = (const float*)d_in[22];
    float* out = (float*)d_out;

    float *ph, *pq, *pk, *pv, *pa, *ppq, *ppk, *pmlp, *pkv, *pz;
    cudaGetSymbolAddress((void**)&ph,   g_h);
    cudaGetSymbolAddress((void**)&pq,   g_q);
    cudaGetSymbolAddress((void**)&pk,   g_k);
    cudaGetSymbolAddress((void**)&pv,   g_v);
    cudaGetSymbolAddress((void**)&pa,   g_a);
    cudaGetSymbolAddress((void**)&ppq,  g_pq);
    cudaGetSymbolAddress((void**)&ppk,  g_pk);
    cudaGetSymbolAddress((void**)&pmlp, g_mlp);
    cudaGetSymbolAddress((void**)&pkv,  g_kv);
    cudaGetSymbolAddress((void**)&pz,   g_z);

    embed_kernel<<<CBS, 128>>>(x, emb, pos);

    for (int l = 0; l < CL; l++) {
        const float* wq = Wq + (long)l * CD * CD;
        const float* wk = Wk + (long)l * CD * CD;
        const float* wv = Wv + (long)l * CD * CD;
        const float* wf = Wf + (long)l * CD * CP;
        const float* wo = Wo + (long)l * CD * CD;
        const float* w1 = W1 + (long)l * CD * CDF;
        const float* w2 = W2 + (long)l * CDF * CD;
        const float* biq = bq + (long)l * CD;
        const float* bik = bk + (long)l * CD;
        const float* biv = bv + (long)l * CD;
        const float* bif = bf + (long)l * CP;
        const float* bio = bo + (long)l * CD;
        const float* bi1 = b1 + (long)l * CDF;
        const float* bi2 = b2 + (long)l * CD;

        dim3 gQKV(CD / 128, CBS / 128, 1);
        tgemm_nn<0><<<gQKV, 256>>>(ph, wq, biq, pq, CBS, CD, CD, 0, 0, 0, nullptr);
        tgemm_nn<0><<<gQKV, 256>>>(ph, wk, bik, pk, CBS, CD, CD, 0, 0, 0, nullptr);
        tgemm_nn<0><<<gQKV, 256>>>(ph, wv, biv, pv, CBS, CD, CD, 0, 0, 0, nullptr);

        dim3 gF(CP / 128, CBS / 128, 1);
        tgemm_nn<1><<<gF, 256>>>(pq, wf, bif, ppq, CBS, CP, CD, 0, 0, 0, nullptr);
        tgemm_nn<1><<<gF, 256>>>(pk, wf, bif, ppk, CBS, CP, CD, 0, 0, 0, nullptr);

        pksum_part_kernel<<<dim3(CB, PKCH), 128>>>();
        pksum_reduce_kernel<<<(CB * CP + 255) / 256, 256>>>();

        sgemm_tn_split<<<dim3(CD / 128, 1, CB * KVSPLIT), 256>>>();
        kv_reduce_kernel<<<(CB * CP * CD + 255) / 256, 256>>>();

        z_kernel<<<CBS / 8, 256>>>();

        // out[b,s,d] = (pq @ kv) / (z + eps)   (batched)
        dim3 gO(CD / 128, CS / 128, CB);
        tgemm_nn<3><<<gO, 256>>>(ppq, pkv, nullptr, pa,
                                 CS, CD, CP,
                                 (long)CS * CP, (long)CP * CD, (long)CS * CD, pz);

        tgemm_nn<0><<<gQKV, 256>>>(pa, wo, bio, pq, CBS, CD, CD, 0, 0, 0, nullptr);

        ln_kernel<<<CBS, 128>>>(pq, lng + (long)l * CD, lnb + (long)l * CD);

        dim3 g1(CDF / 128, CBS / 128, 1);
        tgemm_nn<2><<<g1, 256>>>(pq, w1, bi1, pmlp, CBS, CDF, CD, 0, 0, 0, nullptr);

        dim3 g2(CD / 128, CBS / 128, 1);
        tgemm_nn<0><<<g2, 256>>>(pmlp, w2, bi2, ph, CBS, CD, CDF, 0, 0, 0, nullptr);
    }

    pool_part_kernel<<<dim3(CB, POOLCH), CD>>>();
    pool_reduce_kernel<<<(CB * CD + 255) / 256, 256>>>();
    head1_kernel<<<CB, CDH>>>(Wh1, bh1);
    head2_kernel<<<1, 32>>>(Wh2, bh2, out);
}

// round 16
// speedup vs baseline: 2.6291x; 1.0132x over previous
#include <cuda_runtime.h>
#include <cuda_bf16.h>
#include <math.h>
#include <stdint.h>

// Problem constants
#define CB   8
#define CS   4096
#define CD   512
#define CP   128
#define CL   4
#define CDF  2048
#define CDH  256
#define CC   2
#define CBS  (CB*CS)          // 32768 tokens

#define KVSPLIT 8
#define PKCH    32
#define POOLCH  16

// ---------------- scratch (device globals; no allocation allowed) ----------------
__device__ float g_h   [(size_t)CBS*CD];
__device__ float g_q   [(size_t)CBS*CD];    // Wo output (LN input)
__device__ float g_v   [(size_t)CBS*CD];
__device__ float g_pq  [(size_t)CBS*CP];
__device__ float g_pk  [(size_t)CBS*CP];
__device__ float g_kvp [(size_t)CB*KVSPLIT*CP*CD];
__device__ float g_pks [(size_t)CB*CP];
__device__ float g_pkp [(size_t)PKCH*CB*CP];
__device__ float g_z   [(size_t)CBS];
__device__ float g_pool[(size_t)CB*CD];
__device__ float g_poolp[(size_t)POOLCH*CB*CD];
__device__ float g_h1  [(size_t)CB*CDH];

// bf16 hi/lo activation planes
__device__ __nv_bfloat16 g_hbh [(size_t)CBS*CD],  g_hbl [(size_t)CBS*CD];
__device__ __nv_bfloat16 g_qbh [(size_t)CBS*CD],  g_qbl [(size_t)CBS*CD];
__device__ __nv_bfloat16 g_kbh [(size_t)CBS*CD],  g_kbl [(size_t)CBS*CD];
__device__ __nv_bfloat16 g_abh [(size_t)CBS*CD],  g_abl [(size_t)CBS*CD];
__device__ __nv_bfloat16 g_lnh [(size_t)CBS*CD],  g_lnl [(size_t)CBS*CD];
__device__ __nv_bfloat16 g_mlph[(size_t)CBS*CDF], g_mlpl[(size_t)CBS*CDF];
__device__ __nv_bfloat16 g_pqh [(size_t)CBS*CP],  g_pql [(size_t)CBS*CP];
__device__ __nv_bfloat16 g_kvh [(size_t)CB*CP*CD],g_kvl [(size_t)CB*CP*CD];

// bf16 hi/lo weight planes (all layers)
#define WTOT 12845056
__device__ __nv_bfloat16 g_wh[(size_t)WTOT], g_wl[(size_t)WTOT];

// per-layer weight offsets within g_wh/g_wl
#define WOFS_Q 0L
#define WOFS_K 262144L
#define WOFS_V 524288L
#define WOFS_F 786432L
#define WOFS_O 851968L
#define WOFS_1 1114112L
#define WOFS_2 2162688L
#define WSTR   3211264L

// ---------------- helpers ----------------
__device__ __forceinline__ void split1(float x, __nv_bfloat16& h, __nv_bfloat16& l)
{
    h = __float2bfloat16(x);
    l = __float2bfloat16(x - __bfloat162float(h));
}

// ---------------- weight split ----------------
__global__ void wsplit_kernel(const float* __restrict__ s,
                              __nv_bfloat16* __restrict__ dh,
                              __nv_bfloat16* __restrict__ dl, int n)
{
    int i = (blockIdx.x * blockDim.x + threadIdx.x) * 4;
    if (i >= n) return;
    float4 x = *(const float4*)(s + i);
    __nv_bfloat16 h0,h1,h2,h3,l0,l1,l2,l3;
    split1(x.x,h0,l0); split1(x.y,h1,l1); split1(x.z,h2,l2); split1(x.w,h3,l3);
    *(__nv_bfloat162*)(dh+i)   = __halves2bfloat162(h0,h1);
    *(__nv_bfloat162*)(dh+i+2) = __halves2bfloat162(h2,h3);
    *(__nv_bfloat162*)(dl+i)   = __halves2bfloat162(l0,l1);
    *(__nv_bfloat162*)(dl+i+2) = __halves2bfloat162(l2,l3);
}

// ---------------- embedding (fp32 + hi/lo planes) ----------------
__global__ void embed_kernel(const int* __restrict__ x,
                             const float* __restrict__ emb,
                             const float* __restrict__ pos)
{
    long row = blockIdx.x;
    int  s   = (int)(row & (CS - 1));
    int  tok = x[row];
    int  t   = threadIdx.x;               // 128 threads, float4 each
    float4 e = ((const float4*)(emb + (long)tok * CD))[t];
    float4 p = ((const float4*)(pos + (long)s   * CD))[t];
    float4 o = make_float4(e.x+p.x, e.y+p.y, e.z+p.z, e.w+p.w);
    ((float4*)(g_h + row * CD))[t] = o;
    __nv_bfloat16 h0,h1,h2,h3,l0,l1,l2,l3;
    split1(o.x,h0,l0); split1(o.y,h1,l1); split1(o.z,h2,l2); split1(o.w,h3,l3);
    long base = row * CD + 4L * t;
    *(__nv_bfloat162*)(g_hbh+base)   = __halves2bfloat162(h0,h1);
    *(__nv_bfloat162*)(g_hbh+base+2) = __halves2bfloat162(h2,h3);
    *(__nv_bfloat162*)(g_hbl+base)   = __halves2bfloat162(l0,l1);
    *(__nv_bfloat162*)(g_hbl+base+2) = __halves2bfloat162(l2,l3);
}

// ============ 3xBF16 tensor-core GEMM (NN), 128x128x32, cp.async + ldmatrix ======
// EPI: 0 = +bias ; 1 = elu(+bias)+1 ; 2 = tanh-gelu(+bias) ; 3 = /(z+1e-6), no bias
// OUTF: write fp32 C ; OUTB: write bf16 hi/lo C planes

#define MMA_BF16(d, a, b) \
    asm volatile("mma.sync.aligned.m16n8k16.row.col.f32.bf16.bf16.f32 " \
                 "{%0,%1,%2,%3},{%4,%5,%6,%7},{%8,%9},{%0,%1,%2,%3};" \
                 : "+f"(d[0]), "+f"(d[1]), "+f"(d[2]), "+f"(d[3]) \
                 : "r"(a[0]), "r"(a[1]), "r"(a[2]), "r"(a[3]), \
                   "r"(b[0]), "r"(b[1]))

#define LDSM4(r0,r1,r2,r3,addr) \
    asm volatile("ldmatrix.sync.aligned.m8n8.x4.shared.b16 {%0,%1,%2,%3},[%4];" \
                 : "=r"(r0), "=r"(r1), "=r"(r2), "=r"(r3) : "r"(addr))

#define LDSM2T(r0,r1,addr) \
    asm volatile("ldmatrix.sync.aligned.m8n8.x2.trans.shared.b16 {%0,%1},[%2];" \
                 : "=r"(r0), "=r"(r1) : "r"(addr))

#define CP_ASYNC16(dst, src) \
    asm volatile("cp.async.cg.shared.global [%0], [%1], 16;" :: "r"(dst), "l"(src))
#define CP_COMMIT() asm volatile("cp.async.commit_group;" ::: "memory")
#define CP_WAIT0()  asm volatile("cp.async.wait_group 0;" ::: "memory")

#define ASTR 40    // bf16 units per A smem row (32 + 8 pad)
#define BSTR 136   // bf16 units per B smem row (128 + 8 pad)
// smem stage layout (bytes): AH 0 (10240) | AL 10240 (10240) | BH 20480 (8704) | BL 29184 (8704)
#define STAGE_BYTES 37888u
#define SMEM_BG     (2 * 37888)

template<int EPI, int OUTF, int OUTB>
__global__ __launch_bounds__(256, 2)
void bgemm(const __nv_bfloat16* __restrict__ Ah, const __nv_bfloat16* __restrict__ Al,
           const __nv_bfloat16* __restrict__ Wh, const __nv_bfloat16* __restrict__ Wl,
           const float* __restrict__ bias,
           float* __restrict__ Cf,
           __nv_bfloat16* __restrict__ Cbh, __nv_bfloat16* __restrict__ Cbl,
           int M, int N, int K,
           long sA, long sB, long sC,
           const float* __restrict__ zvec)
{
    extern __shared__ __align__(16) char smem[];
    const uint32_t sb = (uint32_t)__cvta_generic_to_shared(smem);

    const int bz = blockIdx.z;
    Ah += (long)bz * sA;  Al += (long)bz * sA;
    Wh += (long)bz * sB;  Wl += (long)bz * sB;

    const int tid  = threadIdx.x;
    const int lane = tid & 31;
    const int warp = tid >> 5;
    const int wm   = warp & 1;
    const int wn   = warp >> 1;
    const int gp   = lane >> 2;
    const int tg   = lane & 3;

    const int brow = blockIdx.y * 128;
    const int bcol = blockIdx.x * 128;

    // cp.async chunk mapping (2 chunks/thread/plane)
    const int aR0 = tid >> 2,          aC0 = (tid & 3) << 3;        // chunk tid
    const int aR1 = (tid + 256) >> 2,  aC1 = ((tid + 256) & 3) << 3;
    const int bK0 = tid >> 4,          bC0 = (tid & 15) << 3;       // chunk tid
    const int bK1 = (tid + 256) >> 4,  bC1 = ((tid + 256) & 15) << 3;

    float acc[4][4][4];
    #pragma unroll
    for (int mi = 0; mi < 4; mi++)
        #pragma unroll
        for (int ni = 0; ni < 4; ni++)
            #pragma unroll
            for (int r = 0; r < 4; r++) acc[mi][ni][r] = 0.f;

    const int kTiles = K >> 5;

    auto load_stage = [&](int st, int kc) {
        const uint32_t base = sb + (uint32_t)st * STAGE_BYTES;
        // A planes
        uint32_t so = base + (uint32_t)(aR0 * ASTR + aC0) * 2u;
        CP_ASYNC16(so,           Ah + (long)(brow + aR0) * K + kc + aC0);
        CP_ASYNC16(so + 10240u,  Al + (long)(brow + aR0) * K + kc + aC0);
        so = base + (uint32_t)(aR1 * ASTR + aC1) * 2u;
        CP_ASYNC16(so,           Ah + (long)(brow + aR1) * K + kc + aC1);
        CP_ASYNC16(so + 10240u,  Al + (long)(brow + aR1) * K + kc + aC1);
        // B planes
        so = base + 20480u + (uint32_t)(bK0 * BSTR + bC0) * 2u;
        CP_ASYNC16(so,           Wh + (long)(kc + bK0) * N + bcol + bC0);
        CP_ASYNC16(so + 8704u,   Wl + (long)(kc + bK0) * N + bcol + bC0);
        so = base + 20480u + (uint32_t)(bK1 * BSTR + bC1) * 2u;
        CP_ASYNC16(so,           Wh + (long)(kc + bK1) * N + bcol + bC1);
        CP_ASYNC16(so + 8704u,   Wl + (long)(kc + bK1) * N + bcol + bC1);
    };

    const int aldR = lane & 15;
    const int aldK = (lane & 16) ? 8 : 0;

    load_stage(0, 0);
    CP_COMMIT();
    CP_WAIT0();
    __syncthreads();

    for (int c = 0; c < kTiles; c++) {
        const int cur = c & 1;
        const bool has = (c + 1 < kTiles);
        if (has) { load_stage(cur ^ 1, (c + 1) << 5); CP_COMMIT(); }

        const uint32_t base = sb + (uint32_t)cur * STAGE_BYTES;
        #pragma unroll
        for (int ks = 0; ks < 2; ks++) {
            const int kb = ks << 4;
            uint32_t bfh[4][2], bfl[4][2];
            #pragma unroll
            for (int ni = 0; ni < 4; ni++) {
                const uint32_t off = base + 20480u +
                    (uint32_t)(((kb + aldR) * BSTR) + wn * 32 + ni * 8) * 2u;
                LDSM2T(bfh[ni][0], bfh[ni][1], off);
                LDSM2T(bfl[ni][0], bfl[ni][1], off + 8704u);
            }
            #pragma unroll
            for (int mi = 0; mi < 4; mi++) {
                const uint32_t off = base +
                    (uint32_t)(((wm * 64 + mi * 16 + aldR) * ASTR) + kb + aldK) * 2u;
                uint32_t afh[4], afl[4];
                LDSM4(afh[0], afh[1], afh[2], afh[3], off);
                LDSM4(afl[0], afl[1], afl[2], afl[3], off + 10240u);
                #pragma unroll
                for (int ni = 0; ni < 4; ni++) {
                    MMA_BF16(acc[mi][ni], afl, bfh[ni]);
                    MMA_BF16(acc[mi][ni], afh, bfl[ni]);
                    MMA_BF16(acc[mi][ni], afh, bfh[ni]);
                }
            }
        }

        if (has) { CP_WAIT0(); __syncthreads(); }
    }

    // ---------------- epilogue ----------------
    float zr0[4], zr1[4];
    if (EPI == 3) {
        #pragma unroll
        for (int mi = 0; mi < 4; mi++) {
            const int r = brow + wm * 64 + mi * 16 + gp;
            zr0[mi] = 1.f / (zvec[(long)bz * CS + r    ] + 1e-6f);
            zr1[mi] = 1.f / (zvec[(long)bz * CS + r + 8] + 1e-6f);
        }
    }

    #pragma unroll
    for (int ni = 0; ni < 4; ni++) {
        const int cc = bcol + wn * 32 + ni * 8 + 2 * tg;
        float bv0 = 0.f, bv1 = 0.f;
        if (EPI != 3) { bv0 = bias[cc]; bv1 = bias[cc + 1]; }
        #pragma unroll
        for (int mi = 0; mi < 4; mi++) {
            const int r0 = brow + wm * 64 + mi * 16 + gp;
            float v[4];
            v[0] = acc[mi][ni][0] + bv0;
            v[1] = acc[mi][ni][1] + bv1;
            v[2] = acc[mi][ni][2] + bv0;
            v[3] = acc[mi][ni][3] + bv1;
            #pragma unroll
            for (int r = 0; r < 4; r++) {
                float x = v[r];
                if (EPI == 1) {
                    x = (x > 0.f) ? (x + 1.f) : expf(x);
                } else if (EPI == 2) {
                    float u = 0.7978845608028654f * (x + 0.044715f * x * x * x);
                    x = 0.5f * x * (1.f + tanhf(u));
                } else if (EPI == 3) {
                    x = x * ((r < 2) ? zr0[mi] : zr1[mi]);
                }
                v[r] = x;
            }
            const long o0 = (long)bz * sC + (long)r0 * N + cc;
            const long o1 = o0 + 8L * N;
            if (OUTF) {
                *(float2*)(Cf + o0) = make_float2(v[0], v[1]);
                *(float2*)(Cf + o1) = make_float2(v[2], v[3]);
            }
            if (OUTB) {
                __nv_bfloat16 h0,h1,h2,h3,l0,l1,l2,l3;
                split1(v[0],h0,l0); split1(v[1],h1,l1);
                split1(v[2],h2,l2); split1(v[3],h3,l3);
                *(__nv_bfloat162*)(Cbh + o0) = __halves2bfloat162(h0,h1);
                *(__nv_bfloat162*)(Cbh + o1) = __halves2bfloat162(h2,h3);
                *(__nv_bfloat162*)(Cbl + o0) = __halves2bfloat162(l0,l1);
                *(__nv_bfloat162*)(Cbl + o1) = __halves2bfloat162(l2,l3);
            }
        }
    }
}

// ---------------- TN SGEMM for kv = pk^T @ v, deterministic split-K (fp32) ----------------
__global__ __launch_bounds__(256)
void sgemm_tn_split(void)
{
    const int bz    = blockIdx.z;          // b*KVSPLIT + split
    const int b     = bz / KVSPLIT;
    const int split = bz % KVSPLIT;
    const int kBeg  = split * (CS / KVSPLIT);

    const float* A  = g_pk + (long)b * CS * CP;   // [S][P]
    const float* Bm = g_v  + (long)b * CS * CD;   // [S][D]
    float*       Cc = g_kvp + (long)bz * CP * CD;

    const int tid  = threadIdx.x;
    const int bcol = blockIdx.x * 128;     // within D

    __shared__ float As[8][128];
    __shared__ float Bs[8][128];

    const int lRow = tid >> 5;
    const int lCol = (tid & 31) << 2;

    const int mBase = (tid >> 4) << 3;
    const int nBase = (tid & 15) << 3;

    float acc[8][8];
    #pragma unroll
    for (int i = 0; i < 8; i++)
        #pragma unroll
        for (int j = 0; j < 8; j++) acc[i][j] = 0.f;

    for (int k0 = 0; k0 < CS / KVSPLIT; k0 += 8) {
        const long kk = kBeg + k0 + lRow;
        *(float4*)&As[lRow][lCol] = *(const float4*)(A  + kk * CP + lCol);
        *(float4*)&Bs[lRow][lCol] = *(const float4*)(Bm + kk * CD + bcol + lCol);
        __syncthreads();
        #pragma unroll
        for (int k = 0; k < 8; k++) {
            float4 a0 = *(const float4*)&As[k][mBase];
            float4 a1 = *(const float4*)&As[k][mBase+4];
            float4 b0 = *(const float4*)&Bs[k][nBase];
            float4 b1 = *(const float4*)&Bs[k][nBase+4];
            float ra[8] = {a0.x,a0.y,a0.z,a0.w,a1.x,a1.y,a1.z,a1.w};
            float rb[8] = {b0.x,b0.y,b0.z,b0.w,b1.x,b1.y,b1.z,b1.w};
            #pragma unroll
            for (int i = 0; i < 8; i++)
                #pragma unroll
                for (int j = 0; j < 8; j++)
                    acc[i][j] = fmaf(ra[i], rb[j], acc[i][j]);
        }
        __syncthreads();
    }

    #pragma unroll
    for (int i = 0; i < 8; i++) {
        float4* cp = (float4*)(Cc + (long)(mBase + i) * CD + bcol + nBase);
        cp[0] = make_float4(acc[i][0], acc[i][1], acc[i][2], acc[i][3]);
        cp[1] = make_float4(acc[i][4], acc[i][5], acc[i][6], acc[i][7]);
    }
}

// kv reduce -> bf16 hi/lo planes
__global__ void kv_reduce_kernel(void)
{
    long idx = (long)blockIdx.x * blockDim.x + threadIdx.x;   // over CB*CP*CD
    if (idx >= (long)CB * CP * CD) return;
    long b = idx / (CP * CD);
    long r = idx % (CP * CD);
    float s = 0.f;
    #pragma unroll
    for (int sp = 0; sp < KVSPLIT; sp++)
        s += g_kvp[(b * KVSPLIT + sp) * (long)(CP * CD) + r];
    __nv_bfloat16 h, l;
    split1(s, h, l);
    g_kvh[idx] = h;
    g_kvl[idx] = l;
}

// ---------------- pk.sum over S ----------------
__global__ void pksum_part_kernel(void)   // grid (CB, PKCH), block 128
{
    int b = blockIdx.x, ch = blockIdx.y, t = threadIdx.x;
    const int chunk = CS / PKCH;
    float acc = 0.f;
    const float* p = g_pk + ((long)b * CS + (long)ch * chunk) * CP + t;
    for (int s = 0; s < chunk; s++) acc += p[(long)s * CP];
    g_pkp[((long)ch * CB + b) * CP + t] = acc;
}

__global__ void pksum_reduce_kernel(void)
{
    int idx = blockIdx.x * blockDim.x + threadIdx.x;
    if (idx >= CB * CP) return;
    float s = 0.f;
    #pragma unroll
    for (int ch = 0; ch < PKCH; ch++)
        s += g_pkp[(long)ch * CB * CP + idx];
    g_pks[idx] = s;
}

// ---------------- z = pq . pksum (per row) ----------------
__global__ void z_kernel(void)   // grid CBS/8, block 256
{
    const long row  = (long)blockIdx.x * 8 + (threadIdx.x >> 5);
    const int  lane = threadIdx.x & 31;
    const int  b    = (int)(row / CS);
    const float* pr = g_pq  + row * CP;
    const float* ps = g_pks + (long)b * CP;
    float acc = 0.f;
    #pragma unroll
    for (int i = lane; i < CP; i += 32) acc += pr[i] * ps[i];
    #pragma unroll
    for (int o = 16; o; o >>= 1) acc += __shfl_xor_sync(0xffffffffu, acc, o);
    if (lane == 0) g_z[row] = acc;
}

// ---------------- layernorm: fp32 in -> bf16 hi/lo planes out ----------------
__global__ void ln_kernel(const float* __restrict__ X,
                          const float* __restrict__ gamma,
                          const float* __restrict__ beta)
{
    __shared__ float red[128];
    const long row = blockIdx.x;
    const float4* xp = (const float4*)(X + row * CD);
    const int t = threadIdx.x;
    float4 v = xp[t];

    red[t] = v.x + v.y + v.z + v.w;
    __syncthreads();
    for (int o = 64; o; o >>= 1) { if (t < o) red[t] += red[t + o]; __syncthreads(); }
    const float mu = red[0] * (1.f / CD);
    __syncthreads();

    float dx = v.x - mu, dy = v.y - mu, dz = v.z - mu, dw = v.w - mu;
    red[t] = dx*dx + dy*dy + dz*dz + dw*dw;
    __syncthreads();
    for (int o = 64; o; o >>= 1) { if (t < o) red[t] += red[t + o]; __syncthreads(); }
    const float rstd = rsqrtf(red[0] * (1.f / CD) + 1e-5f);

    const float4 g4 = ((const float4*)gamma)[t];
    const float4 b4 = ((const float4*)beta)[t];
    float o0 = dx * rstd * g4.x + b4.x;
    float o1 = dy * rstd * g4.y + b4.y;
    float o2 = dz * rstd * g4.z + b4.z;
    float o3 = dw * rstd * g4.w + b4.w;

    __nv_bfloat16 h0,h1,h2,h3,l0,l1,l2,l3;
    split1(o0,h0,l0); split1(o1,h1,l1); split1(o2,h2,l2); split1(o3,h3,l3);
    long base = row * CD + 4L * t;
    *(__nv_bfloat162*)(g_lnh+base)   = __halves2bfloat162(h0,h1);
    *(__nv_bfloat162*)(g_lnh+base+2) = __halves2bfloat162(h2,h3);
    *(__nv_bfloat162*)(g_lnl+base)   = __halves2bfloat162(l0,l1);
    *(__nv_bfloat162*)(g_lnl+base+2) = __halves2bfloat162(l2,l3);
}

// ---------------- mean pool over S ----------------
__global__ void pool_part_kernel(void)    // grid (CB, POOLCH), block CD
{
    int b = blockIdx.x, ch = blockIdx.y, d = threadIdx.x;
    const int chunk = CS / POOLCH;
    float acc = 0.f;
    const float* p = g_h + ((long)b * CS + (long)ch * chunk) * CD + d;
    for (int s = 0; s < chunk; s++) acc += p[(long)s * CD];
    g_poolp[((long)ch * CB + b) * CD + d] = acc;
}

__global__ void pool_reduce_kernel(void)
{
    int idx = blockIdx.x * blockDim.x + threadIdx.x;
    if (idx >= CB * CD) return;
    float s = 0.f;
    #pragma unroll
    for (int ch = 0; ch < POOLCH; ch++)
        s += g_poolp[(long)ch * CB * CD + idx];
    g_pool[idx] = s * (1.f / CS);
}

// ---------------- head ----------------
__global__ void head1_kernel(const float* __restrict__ Wh1,
                             const float* __restrict__ bh1)
{
    int b = blockIdx.x, t = threadIdx.x;
    const float* pr = g_pool + (long)b * CD;
    float acc = 0.f;
    for (int k = 0; k < CD; k++)
        acc = fmaf(pr[k], Wh1[(long)k * CDH + t], acc);
    float v = acc + bh1[t];
    g_h1[(long)b * CDH + t] = v > 0.f ? v : 0.f;
}

__global__ void head2_kernel(const float* __restrict__ Wh2,
                             const float* __restrict__ bh2,
                             float* __restrict__ out)
{
    int idx = threadIdx.x;
    if (idx >= CB * CC) return;
    int b = idx / CC, c = idx % CC;
    const float* h1 = g_h1 + (long)b * CDH;
    float acc = 0.f;
    for (int k = 0; k < CDH; k++)
        acc = fmaf(h1[k], Wh2[(long)k * CC + c], acc);
    out[idx] = acc + bh2[c];
}

// ---------------- host ----------------
extern "C" void kernel_launch(void* const* d_in, const int* in_sizes, int n_in,
                              void* d_out, int out_size)
{
    (void)in_sizes; (void)n_in; (void)out_size;

    const int*   x    = (const int*)  d_in[0];
    const float* emb  = (const float*)d_in[1];
    const float* pos  = (const float*)d_in[2];
    const float* Wq   = (const float*)d_in[3];
    const float* bq   = (const float*)d_in[4];
    const float* Wk   = (const float*)d_in[5];
    const float* bk   = (const float*)d_in[6];
    const float* Wv   = (const float*)d_in[7];
    const float* bv   = (const float*)d_in[8];
    const float* Wf   = (const float*)d_in[9];
    const float* bf   = (const float*)d_in[10];
    const float* Wo   = (const float*)d_in[11];
    const float* bo   = (const float*)d_in[12];
    const float* lng  = (const float*)d_in[13];
    const float* lnb  = (const float*)d_in[14];
    const float* W1   = (const float*)d_in[15];
    const float* b1   = (const float*)d_in[16];
    const float* W2   = (const float*)d_in[17];
    const float* b2   = (const float*)d_in[18];
    const float* Wh1  = (const float*)d_in[19];
    const float* bh1  = (const float*)d_in[20];
    const float* Wh2  = (const float*)d_in[21];
    const float* bh2  = (const float*)d_in[22];
    float* out = (float*)d_out;

    static bool attr_done = false;
    if (!attr_done) {
        cudaFuncSetAttribute(bgemm<0,0,1>, cudaFuncAttributeMaxDynamicSharedMemorySize, SMEM_BG);
        cudaFuncSetAttribute(bgemm<0,1,0>, cudaFuncAttributeMaxDynamicSharedMemorySize, SMEM_BG);
        cudaFuncSetAttribute(bgemm<0,1,1>, cudaFuncAttributeMaxDynamicSharedMemorySize, SMEM_BG);
        cudaFuncSetAttribute(bgemm<1,1,1>, cudaFuncAttributeMaxDynamicSharedMemorySize, SMEM_BG);
        cudaFuncSetAttribute(bgemm<1,1,0>, cudaFuncAttributeMaxDynamicSharedMemorySize, SMEM_BG);
        cudaFuncSetAttribute(bgemm<3,0,1>, cudaFuncAttributeMaxDynamicSharedMemorySize, SMEM_BG);
        cudaFuncSetAttribute(bgemm<2,0,1>, cudaFuncAttributeMaxDynamicSharedMemorySize, SMEM_BG);
        attr_done = true;
    }

    float *ph, *pWoOut, *pv, *ppq, *ppk, *pz;
    cudaGetSymbolAddress((void**)&ph,     g_h);
    cudaGetSymbolAddress((void**)&pWoOut, g_q);
    cudaGetSymbolAddress((void**)&pv,     g_v);
    cudaGetSymbolAddress((void**)&ppq,    g_pq);
    cudaGetSymbolAddress((void**)&ppk,    g_pk);
    cudaGetSymbolAddress((void**)&pz,     g_z);

    __nv_bfloat16 *hbh,*hbl,*qbh,*qbl,*kbh,*kbl,*abh,*abl,*lnh,*lnl,
                  *mlph,*mlpl,*pqh,*pql,*kvh,*kvl,*pwh,*pwl;
    cudaGetSymbolAddress((void**)&hbh,  g_hbh);  cudaGetSymbolAddress((void**)&hbl,  g_hbl);
    cudaGetSymbolAddress((void**)&qbh,  g_qbh);  cudaGetSymbolAddress((void**)&qbl,  g_qbl);
    cudaGetSymbolAddress((void**)&kbh,  g_kbh);  cudaGetSymbolAddress((void**)&kbl,  g_kbl);
    cudaGetSymbolAddress((void**)&abh,  g_abh);  cudaGetSymbolAddress((void**)&abl,  g_abl);
    cudaGetSymbolAddress((void**)&lnh,  g_lnh);  cudaGetSymbolAddress((void**)&lnl,  g_lnl);
    cudaGetSymbolAddress((void**)&mlph, g_mlph); cudaGetSymbolAddress((void**)&mlpl, g_mlpl);
    cudaGetSymbolAddress((void**)&pqh,  g_pqh);  cudaGetSymbolAddress((void**)&pql,  g_pql);
    cudaGetSymbolAddress((void**)&kvh,  g_kvh);  cudaGetSymbolAddress((void**)&kvl,  g_kvl);
    cudaGetSymbolAddress((void**)&pwh,  g_wh);   cudaGetSymbolAddress((void**)&pwl,  g_wl);

    // ---- split all weights into bf16 hi/lo planes ----
    for (int l = 0; l < CL; l++) {
        const long lw = (long)l * WSTR;
        wsplit_kernel<<<(CD*CD)/1024, 256>>>(Wq + (long)l*CD*CD,  pwh+lw+WOFS_Q, pwl+lw+WOFS_Q, CD*CD);
        wsplit_kernel<<<(CD*CD)/1024, 256>>>(Wk + (long)l*CD*CD,  pwh+lw+WOFS_K, pwl+lw+WOFS_K, CD*CD);
        wsplit_kernel<<<(CD*CD)/1024, 256>>>(Wv + (long)l*CD*CD,  pwh+lw+WOFS_V, pwl+lw+WOFS_V, CD*CD);
        wsplit_kernel<<<(CD*CP)/1024, 256>>>(Wf + (long)l*CD*CP,  pwh+lw+WOFS_F, pwl+lw+WOFS_F, CD*CP);
        wsplit_kernel<<<(CD*CD)/1024, 256>>>(Wo + (long)l*CD*CD,  pwh+lw+WOFS_O, pwl+lw+WOFS_O, CD*CD);
        wsplit_kernel<<<(CD*CDF)/1024, 256>>>(W1 + (long)l*CD*CDF, pwh+lw+WOFS_1, pwl+lw+WOFS_1, CD*CDF);
        wsplit_kernel<<<(CDF*CD)/1024, 256>>>(W2 + (long)l*CDF*CD, pwh+lw+WOFS_2, pwl+lw+WOFS_2, CDF*CD);
    }

    embed_kernel<<<CBS, 128>>>(x, emb, pos);

    for (int l = 0; l < CL; l++) {
        const long lw = (long)l * WSTR;
        const __nv_bfloat16 *wqh = pwh+lw+WOFS_Q, *wql = pwl+lw+WOFS_Q;
        const __nv_bfloat16 *wkh = pwh+lw+WOFS_K, *wkl = pwl+lw+WOFS_K;
        const __nv_bfloat16 *wvh = pwh+lw+WOFS_V, *wvl = pwl+lw+WOFS_V;
        const __nv_bfloat16 *wfh = pwh+lw+WOFS_F, *wfl = pwl+lw+WOFS_F;
        const __nv_bfloat16 *woh = pwh+lw+WOFS_O, *wol = pwl+lw+WOFS_O;
        const __nv_bfloat16 *w1h = pwh+lw+WOFS_1, *w1l = pwl+lw+WOFS_1;
        const __nv_bfloat16 *w2h = pwh+lw+WOFS_2, *w2l = pwl+lw+WOFS_2;
        const float* biq = bq + (long)l * CD;
        const float* bik = bk + (long)l * CD;
        const float* biv = bv + (long)l * CD;
        const float* bif = bf + (long)l * CP;
        const float* bio = bo + (long)l * CD;
        const float* bi1 = b1 + (long)l * CDF;
        const float* bi2 = b2 + (long)l * CD;

        dim3 gQKV(CD / 128, CBS / 128, 1);
        bgemm<0,0,1><<<gQKV, 256, SMEM_BG>>>(hbh, hbl, wqh, wql, biq,
                                             nullptr, qbh, qbl, CBS, CD, CD, 0, 0, 0, nullptr);
        bgemm<0,0,1><<<gQKV, 256, SMEM_BG>>>(hbh, hbl, wkh, wkl, bik,
                                             nullptr, kbh, kbl, CBS, CD, CD, 0, 0, 0, nullptr);
        bgemm<0,1,0><<<gQKV, 256, SMEM_BG>>>(hbh, hbl, wvh, wvl, biv,
                                             pv, nullptr, nullptr, CBS, CD, CD, 0, 0, 0, nullptr);

        dim3 gF(CP / 128, CBS / 128, 1);
        bgemm<1,1,1><<<gF, 256, SMEM_BG>>>(qbh, qbl, wfh, wfl, bif,
                                           ppq, pqh, pql, CBS, CP, CD, 0, 0, 0, nullptr);
        bgemm<1,1,0><<<gF, 256, SMEM_BG>>>(kbh, kbl, wfh, wfl, bif,
                                           ppk, nullptr, nullptr, CBS, CP, CD, 0, 0, 0, nullptr);

        pksum_part_kernel<<<dim3(CB, PKCH), 128>>>();
        pksum_reduce_kernel<<<(CB * CP + 255) / 256, 256>>>();

        sgemm_tn_split<<<dim3(CD / 128, 1, CB * KVSPLIT), 256>>>();
        kv_reduce_kernel<<<(CB * CP * CD + 255) / 256, 256>>>();

        z_kernel<<<CBS / 8, 256>>>();

        // out[b,s,d] = (pq @ kv) / (z + eps)   (batched, bf16 planes)
        dim3 gO(CD / 128, CS / 128, CB);
        bgemm<3,0,1><<<gO, 256, SMEM_BG>>>(pqh, pql, kvh, kvl, nullptr,
                                           nullptr, abh, abl, CS, CD, CP,
                                           (long)CS * CP, (long)CP * CD, (long)CS * CD, pz);

        bgemm<0,1,0><<<gQKV, 256, SMEM_BG>>>(abh, abl, woh, wol, bio,
                                             pWoOut, nullptr, nullptr, CBS, CD, CD, 0, 0, 0, nullptr);

        ln_kernel<<<CBS, 128>>>(pWoOut, lng + (long)l * CD, lnb + (long)l * CD);

        dim3 g1(CDF / 128, CBS / 128, 1);
        bgemm<2,0,1><<<g1, 256, SMEM_BG>>>(lnh, lnl, w1h, w1l, bi1,
                                           nullptr, mlph, mlpl, CBS, CDF, CD, 0, 0, 0, nullptr);

        dim3 g2(CD / 128, CBS / 128, 1);
        bgemm<0,1,1><<<g2, 256, SMEM_BG>>>(mlph, mlpl, w2h, w2l, bi2,
                                           ph, hbh, hbl, CBS, CD, CDF, 0, 0, 0, nullptr);
    }

    pool_part_kernel<<<dim3(CB, POOLCH), CD>>>();
    pool_reduce_kernel<<<(CB * CD + 255) / 256, 256>>>();
    head1_kernel<<<CB, CDH>>>(Wh1, bh1);
    head2_kernel<<<1, 32>>>(Wh2, bh2, out);
}

// round 17
// speedup vs baseline: 2.7036x; 1.0283x over previous
#include <cuda_runtime.h>
#include <cuda_bf16.h>
#include <math.h>
#include <stdint.h>

// Problem constants
#define CB   8
#define CS   4096
#define CD   512
#define CP   128
#define CL   4
#define CDF  2048
#define CDH  256
#define CC   2
#define CBS  (CB*CS)          // 32768 tokens

#define KVSPLIT 8
#define PKCH    32
#define POOLCH  16

// ---------------- scratch (device globals; no allocation allowed) ----------------
__device__ float g_h   [(size_t)CBS*CD];
__device__ float g_q   [(size_t)CBS*CD];    // Wo output (LN input)
__device__ float g_v   [(size_t)CBS*CD];
__device__ float g_pq  [(size_t)CBS*CP];
__device__ float g_pk  [(size_t)CBS*CP];
__device__ float g_kvp [(size_t)CB*KVSPLIT*CP*CD];
__device__ float g_pks [(size_t)CB*CP];
__device__ float g_pkp [(size_t)PKCH*CB*CP];
__device__ float g_z   [(size_t)CBS];
__device__ float g_pool[(size_t)CB*CD];
__device__ float g_poolp[(size_t)POOLCH*CB*CD];
__device__ float g_h1  [(size_t)CB*CDH];

// bf16 hi/lo activation planes
__device__ __nv_bfloat16 g_hbh [(size_t)CBS*CD],  g_hbl [(size_t)CBS*CD];
__device__ __nv_bfloat16 g_qbh [(size_t)CBS*CD],  g_qbl [(size_t)CBS*CD];
__device__ __nv_bfloat16 g_kbh [(size_t)CBS*CD],  g_kbl [(size_t)CBS*CD];
__device__ __nv_bfloat16 g_abh [(size_t)CBS*CD],  g_abl [(size_t)CBS*CD];
__device__ __nv_bfloat16 g_lnh [(size_t)CBS*CD],  g_lnl [(size_t)CBS*CD];
__device__ __nv_bfloat16 g_mlph[(size_t)CBS*CDF], g_mlpl[(size_t)CBS*CDF];
__device__ __nv_bfloat16 g_pqh [(size_t)CBS*CP],  g_pql [(size_t)CBS*CP];
__device__ __nv_bfloat16 g_kvh [(size_t)CB*CP*CD],g_kvl [(size_t)CB*CP*CD];

// bf16 hi/lo weight planes (all layers)
#define WTOT 12845056
__device__ __nv_bfloat16 g_wh[(size_t)WTOT], g_wl[(size_t)WTOT];

// per-layer weight offsets within g_wh/g_wl
#define WOFS_Q 0L
#define WOFS_K 262144L
#define WOFS_V 524288L
#define WOFS_F 786432L
#define WOFS_O 851968L
#define WOFS_1 1114112L
#define WOFS_2 2162688L
#define WSTR   3211264L

// layer-contiguous blocks for the 7 weight types (each [L, ...] contiguous in src)
// we store them layer-strided; the wsplit kernel handles the layer re-offsetting

// ---------------- helpers ----------------
__device__ __forceinline__ void split1(float x, __nv_bfloat16& h, __nv_bfloat16& l)
{
    h = __float2bfloat16(x);
    l = __float2bfloat16(x - __bfloat162float(h));
}

// ---------------- weight split: all L layers of one weight type ----------------
__global__ void wsplit_kernel(const float* __restrict__ s,
                              __nv_bfloat16* __restrict__ dh,
                              __nv_bfloat16* __restrict__ dl,
                              int perLayer, long wofs)
{
    long i = ((long)blockIdx.x * blockDim.x + threadIdx.x) * 4;
    if (i >= (long)perLayer * CL) return;
    int  l  = (int)(i / perLayer);
    long r  = i - (long)l * perLayer;
    float4 x = *(const float4*)(s + i);
    long o = (long)l * WSTR + wofs + r;
    __nv_bfloat16 h0,h1,h2,h3,l0,l1,l2,l3;
    split1(x.x,h0,l0); split1(x.y,h1,l1); split1(x.z,h2,l2); split1(x.w,h3,l3);
    *(__nv_bfloat162*)(dh+o)   = __halves2bfloat162(h0,h1);
    *(__nv_bfloat162*)(dh+o+2) = __halves2bfloat162(h2,h3);
    *(__nv_bfloat162*)(dl+o)   = __halves2bfloat162(l0,l1);
    *(__nv_bfloat162*)(dl+o+2) = __halves2bfloat162(l2,l3);
}

// ---------------- embedding (fp32 + hi/lo planes) ----------------
__global__ void embed_kernel(const int* __restrict__ x,
                             const float* __restrict__ emb,
                             const float* __restrict__ pos)
{
    long row = blockIdx.x;
    int  s   = (int)(row & (CS - 1));
    int  tok = x[row];
    int  t   = threadIdx.x;               // 128 threads, float4 each
    float4 e = ((const float4*)(emb + (long)tok * CD))[t];
    float4 p = ((const float4*)(pos + (long)s   * CD))[t];
    float4 o = make_float4(e.x+p.x, e.y+p.y, e.z+p.z, e.w+p.w);
    ((float4*)(g_h + row * CD))[t] = o;
    __nv_bfloat16 h0,h1,h2,h3,l0,l1,l2,l3;
    split1(o.x,h0,l0); split1(o.y,h1,l1); split1(o.z,h2,l2); split1(o.w,h3,l3);
    long base = row * CD + 4L * t;
    *(__nv_bfloat162*)(g_hbh+base)   = __halves2bfloat162(h0,h1);
    *(__nv_bfloat162*)(g_hbh+base+2) = __halves2bfloat162(h2,h3);
    *(__nv_bfloat162*)(g_hbl+base)   = __halves2bfloat162(l0,l1);
    *(__nv_bfloat162*)(g_hbl+base+2) = __halves2bfloat162(l2,l3);
}

// ============ 3xBF16 tensor-core GEMM (NN), 128x128x32, cp.async + ldmatrix ======
// EPI: 0 = +bias ; 1 = elu(+bias)+1 ; 2 = tanh-gelu(+bias) ; 3 = /(z+1e-6), no bias
// OUTF: write fp32 C ; OUTB: write bf16 hi/lo C planes
// Term-major MMA order breaks the 3-MMA accumulator RAW chain.

#define MMA_BF16(d, a, b) \
    asm volatile("mma.sync.aligned.m16n8k16.row.col.f32.bf16.bf16.f32 " \
                 "{%0,%1,%2,%3},{%4,%5,%6,%7},{%8,%9},{%0,%1,%2,%3};" \
                 : "+f"(d[0]), "+f"(d[1]), "+f"(d[2]), "+f"(d[3]) \
                 : "r"(a[0]), "r"(a[1]), "r"(a[2]), "r"(a[3]), \
                   "r"(b[0]), "r"(b[1]))

#define LDSM4(r0,r1,r2,r3,addr) \
    asm volatile("ldmatrix.sync.aligned.m8n8.x4.shared.b16 {%0,%1,%2,%3},[%4];" \
                 : "=r"(r0), "=r"(r1), "=r"(r2), "=r"(r3) : "r"(addr))

#define LDSM4T(r0,r1,r2,r3,addr) \
    asm volatile("ldmatrix.sync.aligned.m8n8.x4.trans.shared.b16 {%0,%1,%2,%3},[%4];" \
                 : "=r"(r0), "=r"(r1), "=r"(r2), "=r"(r3) : "r"(addr))

#define CP_ASYNC16(dst, src) \
    asm volatile("cp.async.cg.shared.global [%0], [%1], 16;" :: "r"(dst), "l"(src))
#define CP_COMMIT() asm volatile("cp.async.commit_group;" ::: "memory")
#define CP_WAIT0()  asm volatile("cp.async.wait_group 0;" ::: "memory")

#define ASTR 40    // bf16 units per A smem row (32 + 8 pad)
#define BSTR 136   // bf16 units per B smem row (128 + 8 pad)
// smem stage layout (bytes): AH 0 (10240) | AL 10240 (10240) | BH 20480 (8704) | BL 29184 (8704)
#define STAGE_BYTES 37888u
#define SMEM_BG     (2 * 37888)

template<int EPI, int OUTF, int OUTB>
__global__ __launch_bounds__(256, 2)
void bgemm(const __nv_bfloat16* __restrict__ Ah, const __nv_bfloat16* __restrict__ Al,
           const __nv_bfloat16* __restrict__ Wh, const __nv_bfloat16* __restrict__ Wl,
           const float* __restrict__ bias,
           float* __restrict__ Cf,
           __nv_bfloat16* __restrict__ Cbh, __nv_bfloat16* __restrict__ Cbl,
           int M, int N, int K,
           long sA, long sB, long sC,
           const float* __restrict__ zvec)
{
    extern __shared__ __align__(16) char smem[];
    const uint32_t sb = (uint32_t)__cvta_generic_to_shared(smem);

    const int bz = blockIdx.z;
    Ah += (long)bz * sA;  Al += (long)bz * sA;
    Wh += (long)bz * sB;  Wl += (long)bz * sB;

    const int tid  = threadIdx.x;
    const int lane = tid & 31;
    const int warp = tid >> 5;
    const int wm   = warp & 1;
    const int wn   = warp >> 1;
    const int gp   = lane >> 2;
    const int tg   = lane & 3;

    const int brow = blockIdx.y * 128;
    const int bcol = blockIdx.x * 128;

    // cp.async chunk mapping (2 chunks/thread/plane)
    const int aR0 = tid >> 2,          aC0 = (tid & 3) << 3;
    const int aR1 = (tid + 256) >> 2,  aC1 = ((tid + 256) & 3) << 3;
    const int bK0 = tid >> 4,          bC0 = (tid & 15) << 3;
    const int bK1 = (tid + 256) >> 4,  bC1 = ((tid + 256) & 15) << 3;

    float acc[4][4][4];
    #pragma unroll
    for (int mi = 0; mi < 4; mi++)
        #pragma unroll
        for (int ni = 0; ni < 4; ni++)
            #pragma unroll
            for (int r = 0; r < 4; r++) acc[mi][ni][r] = 0.f;

    const int kTiles = K >> 5;

    auto load_stage = [&](int st, int kc) {
        const uint32_t base = sb + (uint32_t)st * STAGE_BYTES;
        uint32_t so = base + (uint32_t)(aR0 * ASTR + aC0) * 2u;
        CP_ASYNC16(so,           Ah + (long)(brow + aR0) * K + kc + aC0);
        CP_ASYNC16(so + 10240u,  Al + (long)(brow + aR0) * K + kc + aC0);
        so = base + (uint32_t)(aR1 * ASTR + aC1) * 2u;
        CP_ASYNC16(so,           Ah + (long)(brow + aR1) * K + kc + aC1);
        CP_ASYNC16(so + 10240u,  Al + (long)(brow + aR1) * K + kc + aC1);
        so = base + 20480u + (uint32_t)(bK0 * BSTR + bC0) * 2u;
        CP_ASYNC16(so,           Wh + (long)(kc + bK0) * N + bcol + bC0);
        CP_ASYNC16(so + 8704u,   Wl + (long)(kc + bK0) * N + bcol + bC0);
        so = base + 20480u + (uint32_t)(bK1 * BSTR + bC1) * 2u;
        CP_ASYNC16(so,           Wh + (long)(kc + bK1) * N + bcol + bC1);
        CP_ASYNC16(so + 8704u,   Wl + (long)(kc + bK1) * N + bcol + bC1);
    };

    const int aldR = lane & 15;
    const int aldK = (lane & 16) ? 8 : 0;
    // B x4.trans lane mapping: 4 groups of 8 lanes -> (k half, col half)
    const int bg   = lane >> 3;                 // 0..3
    const int bRow = (lane & 7) + ((bg & 1) << 3);   // k offset within 16
    const int bCol = (bg >> 1) << 3;                  // 0 or 8

    load_stage(0, 0);
    CP_COMMIT();
    CP_WAIT0();
    __syncthreads();

    for (int c = 0; c < kTiles; c++) {
        const int cur = c & 1;
        const bool has = (c + 1 < kTiles);
        if (has) { load_stage(cur ^ 1, (c + 1) << 5); CP_COMMIT(); }

        const uint32_t base = sb + (uint32_t)cur * STAGE_BYTES;
        #pragma unroll
        for (int ks = 0; ks < 2; ks++) {
            const int kb = ks << 4;
            // B fragments: 2 x LDSM4T per plane (covers ni pairs)
            uint32_t bfh[4][2], bfl[4][2];
            #pragma unroll
            for (int np = 0; np < 2; np++) {
                const uint32_t off = base + 20480u +
                    (uint32_t)((kb + bRow) * BSTR + wn * 32 + np * 16 + bCol) * 2u;
                LDSM4T(bfh[2*np][0], bfh[2*np][1], bfh[2*np+1][0], bfh[2*np+1][1], off);
                LDSM4T(bfl[2*np][0], bfl[2*np][1], bfl[2*np+1][0], bfl[2*np+1][1], off + 8704u);
            }
            // A fragments + term-major MMAs, mi-pair at a time
            #pragma unroll
            for (int mp = 0; mp < 2; mp++) {
                uint32_t afh[2][4], afl[2][4];
                #pragma unroll
                for (int m2 = 0; m2 < 2; m2++) {
                    const int mi = mp * 2 + m2;
                    const uint32_t off = base +
                        (uint32_t)((wm * 64 + mi * 16 + aldR) * ASTR + kb + aldK) * 2u;
                    LDSM4(afh[m2][0], afh[m2][1], afh[m2][2], afh[m2][3], off);
                    LDSM4(afl[m2][0], afl[m2][1], afl[m2][2], afl[m2][3], off + 10240u);
                }
                // term 1: al*bh  (8 independent MMAs)
                #pragma unroll
                for (int m2 = 0; m2 < 2; m2++)
                    #pragma unroll
                    for (int ni = 0; ni < 4; ni++)
                        MMA_BF16(acc[mp*2+m2][ni], afl[m2], bfh[ni]);
                // term 2: ah*bl
                #pragma unroll
                for (int m2 = 0; m2 < 2; m2++)
                    #pragma unroll
                    for (int ni = 0; ni < 4; ni++)
                        MMA_BF16(acc[mp*2+m2][ni], afh[m2], bfl[ni]);
                // term 3: ah*bh
                #pragma unroll
                for (int m2 = 0; m2 < 2; m2++)
                    #pragma unroll
                    for (int ni = 0; ni < 4; ni++)
                        MMA_BF16(acc[mp*2+m2][ni], afh[m2], bfh[ni]);
            }
        }

        if (has) { CP_WAIT0(); __syncthreads(); }
    }

    // ---------------- epilogue ----------------
    float zr0[4], zr1[4];
    if (EPI == 3) {
        #pragma unroll
        for (int mi = 0; mi < 4; mi++) {
            const int r = brow + wm * 64 + mi * 16 + gp;
            zr0[mi] = 1.f / (zvec[(long)bz * CS + r    ] + 1e-6f);
            zr1[mi] = 1.f / (zvec[(long)bz * CS + r + 8] + 1e-6f);
        }
    }

    #pragma unroll
    for (int ni = 0; ni < 4; ni++) {
        const int cc = bcol + wn * 32 + ni * 8 + 2 * tg;
        float bv0 = 0.f, bv1 = 0.f;
        if (EPI != 3) { bv0 = bias[cc]; bv1 = bias[cc + 1]; }
        #pragma unroll
        for (int mi = 0; mi < 4; mi++) {
            const int r0 = brow + wm * 64 + mi * 16 + gp;
            float v[4];
            v[0] = acc[mi][ni][0] + bv0;
            v[1] = acc[mi][ni][1] + bv1;
            v[2] = acc[mi][ni][2] + bv0;
            v[3] = acc[mi][ni][3] + bv1;
            #pragma unroll
            for (int r = 0; r < 4; r++) {
                float x = v[r];
                if (EPI == 1) {
                    x = (x > 0.f) ? (x + 1.f) : expf(x);
                } else if (EPI == 2) {
                    float u = 0.7978845608028654f * (x + 0.044715f * x * x * x);
                    x = 0.5f * x * (1.f + tanhf(u));
                } else if (EPI == 3) {
                    x = x * ((r < 2) ? zr0[mi] : zr1[mi]);
                }
                v[r] = x;
            }
            const long o0 = (long)bz * sC + (long)r0 * N + cc;
            const long o1 = o0 + 8L * N;
            if (OUTF) {
                *(float2*)(Cf + o0) = make_float2(v[0], v[1]);
                *(float2*)(Cf + o1) = make_float2(v[2], v[3]);
            }
            if (OUTB) {
                __nv_bfloat16 h0,h1,h2,h3,l0,l1,l2,l3;
                split1(v[0],h0,l0); split1(v[1],h1,l1);
                split1(v[2],h2,l2); split1(v[3],h3,l3);
                *(__nv_bfloat162*)(Cbh + o0) = __halves2bfloat162(h0,h1);
                *(__nv_bfloat162*)(Cbh + o1) = __halves2bfloat162(h2,h3);
                *(__nv_bfloat162*)(Cbl + o0) = __halves2bfloat162(l0,l1);
                *(__nv_bfloat162*)(Cbl + o1) = __halves2bfloat162(l2,l3);
            }
        }
    }
}

// ---------------- TN SGEMM for kv = pk^T @ v, deterministic split-K (fp32) ----------------
__global__ __launch_bounds__(256)
void sgemm_tn_split(void)
{
    const int bz    = blockIdx.z;          // b*KVSPLIT + split
    const int b     = bz / KVSPLIT;
    const int split = bz % KVSPLIT;
    const int kBeg  = split * (CS / KVSPLIT);

    const float* A  = g_pk + (long)b * CS * CP;   // [S][P]
    const float* Bm = g_v  + (long)b * CS * CD;   // [S][D]
    float*       Cc = g_kvp + (long)bz * CP * CD;

    const int tid  = threadIdx.x;
    const int bcol = blockIdx.x * 128;     // within D

    __shared__ float As[8][128];
    __shared__ float Bs[8][128];

    const int lRow = tid >> 5;
    const int lCol = (tid & 31) << 2;

    const int mBase = (tid >> 4) << 3;
    const int nBase = (tid & 15) << 3;

    float acc[8][8];
    #pragma unroll
    for (int i = 0; i < 8; i++)
        #pragma unroll
        for (int j = 0; j < 8; j++) acc[i][j] = 0.f;

    for (int k0 = 0; k0 < CS / KVSPLIT; k0 += 8) {
        const long kk = kBeg + k0 + lRow;
        *(float4*)&As[lRow][lCol] = *(const float4*)(A  + kk * CP + lCol);
        *(float4*)&Bs[lRow][lCol] = *(const float4*)(Bm + kk * CD + bcol + lCol);
        __syncthreads();
        #pragma unroll
        for (int k = 0; k < 8; k++) {
            float4 a0 = *(const float4*)&As[k][mBase];
            float4 a1 = *(const float4*)&As[k][mBase+4];
            float4 b0 = *(const float4*)&Bs[k][nBase];
            float4 b1 = *(const float4*)&Bs[k][nBase+4];
            float ra[8] = {a0.x,a0.y,a0.z,a0.w,a1.x,a1.y,a1.z,a1.w};
            float rb[8] = {b0.x,b0.y,b0.z,b0.w,b1.x,b1.y,b1.z,b1.w};
            #pragma unroll
            for (int i = 0; i < 8; i++)
                #pragma unroll
                for (int j = 0; j < 8; j++)
                    acc[i][j] = fmaf(ra[i], rb[j], acc[i][j]);
        }
        __syncthreads();
    }

    #pragma unroll
    for (int i = 0; i < 8; i++) {
        float4* cp = (float4*)(Cc + (long)(mBase + i) * CD + bcol + nBase);
        cp[0] = make_float4(acc[i][0], acc[i][1], acc[i][2], acc[i][3]);
        cp[1] = make_float4(acc[i][4], acc[i][5], acc[i][6], acc[i][7]);
    }
}

// kv reduce -> bf16 hi/lo planes
__global__ void kv_reduce_kernel(void)
{
    long idx = (long)blockIdx.x * blockDim.x + threadIdx.x;   // over CB*CP*CD
    if (idx >= (long)CB * CP * CD) return;
    long b = idx / (CP * CD);
    long r = idx % (CP * CD);
    float s = 0.f;
    #pragma unroll
    for (int sp = 0; sp < KVSPLIT; sp++)
        s += g_kvp[(b * KVSPLIT + sp) * (long)(CP * CD) + r];
    __nv_bfloat16 h, l;
    split1(s, h, l);
    g_kvh[idx] = h;
    g_kvl[idx] = l;
}

// ---------------- pk.sum over S ----------------
__global__ void pksum_part_kernel(void)   // grid (CB, PKCH), block 128
{
    int b = blockIdx.x, ch = blockIdx.y, t = threadIdx.x;
    const int chunk = CS / PKCH;
    float acc = 0.f;
    const float* p = g_pk + ((long)b * CS + (long)ch * chunk) * CP + t;
    for (int s = 0; s < chunk; s++) acc += p[(long)s * CP];
    g_pkp[((long)ch * CB + b) * CP + t] = acc;
}

__global__ void pksum_reduce_kernel(void)
{
    int idx = blockIdx.x * blockDim.x + threadIdx.x;
    if (idx >= CB * CP) return;
    float s = 0.f;
    #pragma unroll
    for (int ch = 0; ch < PKCH; ch++)
        s += g_pkp[(long)ch * CB * CP + idx];
    g_pks[idx] = s;
}

// ---------------- z = pq . pksum (per row) ----------------
__global__ void z_kernel(void)   // grid CBS/8, block 256
{
    const long row  = (long)blockIdx.x * 8 + (threadIdx.x >> 5);
    const int  lane = threadIdx.x & 31;
    const int  b    = (int)(row / CS);
    const float* pr = g_pq  + row * CP;
    const float* ps = g_pks + (long)b * CP;
    float acc = 0.f;
    #pragma unroll
    for (int i = lane; i < CP; i += 32) acc += pr[i] * ps[i];
    #pragma unroll
    for (int o = 16; o; o >>= 1) acc += __shfl_xor_sync(0xffffffffu, acc, o);
    if (lane == 0) g_z[row] = acc;
}

// ---------------- layernorm: fp32 in -> bf16 hi/lo planes out ----------------
__global__ void ln_kernel(const float* __restrict__ X,
                          const float* __restrict__ gamma,
                          const float* __restrict__ beta)
{
    __shared__ float red[128];
    const long row = blockIdx.x;
    const float4* xp = (const float4*)(X + row * CD);
    const int t = threadIdx.x;
    float4 v = xp[t];

    red[t] = v.x + v.y + v.z + v.w;
    __syncthreads();
    for (int o = 64; o; o >>= 1) { if (t < o) red[t] += red[t + o]; __syncthreads(); }
    const float mu = red[0] * (1.f / CD);
    __syncthreads();

    float dx = v.x - mu, dy = v.y - mu, dz = v.z - mu, dw = v.w - mu;
    red[t] = dx*dx + dy*dy + dz*dz + dw*dw;
    __syncthreads();
    for (int o = 64; o; o >>= 1) { if (t < o) red[t] += red[t + o]; __syncthreads(); }
    const float rstd = rsqrtf(red[0] * (1.f / CD) + 1e-5f);

    const float4 g4 = ((const float4*)gamma)[t];
    const float4 b4 = ((const float4*)beta)[t];
    float o0 = dx * rstd * g4.x + b4.x;
    float o1 = dy * rstd * g4.y + b4.y;
    float o2 = dz * rstd * g4.z + b4.z;
    float o3 = dw * rstd * g4.w + b4.w;

    __nv_bfloat16 h0,h1,h2,h3,l0,l1,l2,l3;
    split1(o0,h0,l0); split1(o1,h1,l1); split1(o2,h2,l2); split1(o3,h3,l3);
    long base = row * CD + 4L * t;
    *(__nv_bfloat162*)(g_lnh+base)   = __halves2bfloat162(h0,h1);
    *(__nv_bfloat162*)(g_lnh+base+2) = __halves2bfloat162(h2,h3);
    *(__nv_bfloat162*)(g_lnl+base)   = __halves2bfloat162(l0,l1);
    *(__nv_bfloat162*)(g_lnl+base+2) = __halves2bfloat162(l2,l3);
}

// ---------------- mean pool over S ----------------
__global__ void pool_part_kernel(void)    // grid (CB, POOLCH), block CD
{
    int b = blockIdx.x, ch = blockIdx.y, d = threadIdx.x;
    const int chunk = CS / POOLCH;
    float acc = 0.f;
    const float* p = g_h + ((long)b * CS + (long)ch * chunk) * CD + d;
    for (int s = 0; s < chunk; s++) acc += p[(long)s * CD];
    g_poolp[((long)ch * CB + b) * CD + d] = acc;
}

__global__ void pool_reduce_kernel(void)
{
    int idx = blockIdx.x * blockDim.x + threadIdx.x;
    if (idx >= CB * CD) return;
    float s = 0.f;
    #pragma unroll
    for (int ch = 0; ch < POOLCH; ch++)
        s += g_poolp[(long)ch * CB * CD + idx];
    g_pool[idx] = s * (1.f / CS);
}

// ---------------- head ----------------
__global__ void head1_kernel(const float* __restrict__ Wh1,
                             const float* __restrict__ bh1)
{
    int b = blockIdx.x, t = threadIdx.x;
    const float* pr = g_pool + (long)b * CD;
    float acc = 0.f;
    for (int k = 0; k < CD; k++)
        acc = fmaf(pr[k], Wh1[(long)k * CDH + t], acc);
    float v = acc + bh1[t];
    g_h1[(long)b * CDH + t] = v > 0.f ? v : 0.f;
}

__global__ void head2_kernel(const float* __restrict__ Wh2,
                             const float* __restrict__ bh2,
                             float* __restrict__ out)
{
    int idx = threadIdx.x;
    if (idx >= CB * CC) return;
    int b = idx / CC, c = idx % CC;
    const float* h1 = g_h1 + (long)b * CDH;
    float acc = 0.f;
    for (int k = 0; k < CDH; k++)
        acc = fmaf(h1[k], Wh2[(long)k * CC + c], acc);
    out[idx] = acc + bh2[c];
}

// ---------------- host ----------------
extern "C" void kernel_launch(void* const* d_in, const int* in_sizes, int n_in,
                              void* d_out, int out_size)
{
    (void)in_sizes; (void)n_in; (void)out_size;

    const int*   x    = (const int*)  d_in[0];
    const float* emb  = (const float*)d_in[1];
    const float* pos  = (const float*)d_in[2];
    const float* Wq   = (const float*)d_in[3];
    const float* bq   = (const float*)d_in[4];
    const float* Wk   = (const float*)d_in[5];
    const float* bk   = (const float*)d_in[6];
    const float* Wv   = (const float*)d_in[7];
    const float* bv   = (const float*)d_in[8];
    const float* Wf   = (const float*)d_in[9];
    const float* bf   = (const float*)d_in[10];
    const float* Wo   = (const float*)d_in[11];
    const float* bo   = (const float*)d_in[12];
    const float* lng  = (const float*)d_in[13];
    const float* lnb  = (const float*)d_in[14];
    const float* W1   = (const float*)d_in[15];
    const float* b1   = (const float*)d_in[16];
    const float* W2   = (const float*)d_in[17];
    const float* b2   = (const float*)d_in[18];
    const float* Wh1  = (const float*)d_in[19];
    const float* bh1  = (const float*)d_in[20];
    const float* Wh2  = (const float*)d_in[21];
    const float* bh2  = (const float*)d_in[22];
    float* out = (float*)d_out;

    static bool attr_done = false;
    if (!attr_done) {
        cudaFuncSetAttribute(bgemm<0,0,1>, cudaFuncAttributeMaxDynamicSharedMemorySize, SMEM_BG);
        cudaFuncSetAttribute(bgemm<0,1,0>, cudaFuncAttributeMaxDynamicSharedMemorySize, SMEM_BG);
        cudaFuncSetAttribute(bgemm<0,1,1>, cudaFuncAttributeMaxDynamicSharedMemorySize, SMEM_BG);
        cudaFuncSetAttribute(bgemm<1,1,1>, cudaFuncAttributeMaxDynamicSharedMemorySize, SMEM_BG);
        cudaFuncSetAttribute(bgemm<1,1,0>, cudaFuncAttributeMaxDynamicSharedMemorySize, SMEM_BG);
        cudaFuncSetAttribute(bgemm<3,0,1>, cudaFuncAttributeMaxDynamicSharedMemorySize, SMEM_BG);
        cudaFuncSetAttribute(bgemm<2,0,1>, cudaFuncAttributeMaxDynamicSharedMemorySize, SMEM_BG);
        attr_done = true;
    }

    float *ph, *pWoOut, *pv, *ppq, *ppk, *pz;
    cudaGetSymbolAddress((void**)&ph,     g_h);
    cudaGetSymbolAddress((void**)&pWoOut, g_q);
    cudaGetSymbolAddress((void**)&pv,     g_v);
    cudaGetSymbolAddress((void**)&ppq,    g_pq);
    cudaGetSymbolAddress((void**)&ppk,    g_pk);
    cudaGetSymbolAddress((void**)&pz,     g_z);

    __nv_bfloat16 *hbh,*hbl,*qbh,*qbl,*kbh,*kbl,*abh,*abl,*lnh,*lnl,
                  *mlph,*mlpl,*pqh,*pql,*kvh,*kvl,*pwh,*pwl;
    cudaGetSymbolAddress((void**)&hbh,  g_hbh);  cudaGetSymbolAddress((void**)&hbl,  g_hbl);
    cudaGetSymbolAddress((void**)&qbh,  g_qbh);  cudaGetSymbolAddress((void**)&qbl,  g_qbl);
    cudaGetSymbolAddress((void**)&kbh,  g_kbh);  cudaGetSymbolAddress((void**)&kbl,  g_kbl);
    cudaGetSymbolAddress((void**)&abh,  g_abh);  cudaGetSymbolAddress((void**)&abl,  g_abl);
    cudaGetSymbolAddress((void**)&lnh,  g_lnh);  cudaGetSymbolAddress((void**)&lnl,  g_lnl);
    cudaGetSymbolAddress((void**)&mlph, g_mlph); cudaGetSymbolAddress((void**)&mlpl, g_mlpl);
    cudaGetSymbolAddress((void**)&pqh,  g_pqh);  cudaGetSymbolAddress((void**)&pql,  g_pql);
    cudaGetSymbolAddress((void**)&kvh,  g_kvh);  cudaGetSymbolAddress((void**)&kvl,  g_kvl);
    cudaGetSymbolAddress((void**)&pwh,  g_wh);   cudaGetSymbolAddress((void**)&pwl,  g_wl);

    // ---- split all weights into bf16 hi/lo planes (7 launches, all layers each) ----
    {
        const int t = 256;
        wsplit_kernel<<<((long)CL*CD*CD/4 + t-1)/t, t>>>(Wq, pwh, pwl, CD*CD,  WOFS_Q);
        wsplit_kernel<<<((long)CL*CD*CD/4 + t-1)/t, t>>>(Wk, pwh, pwl, CD*CD,  WOFS_K);
        wsplit_kernel<<<((long)CL*CD*CD/4 + t-1)/t, t>>>(Wv, pwh, pwl, CD*CD,  WOFS_V);
        wsplit_kernel<<<((long)CL*CD*CP/4 + t-1)/t, t>>>(Wf, pwh, pwl, CD*CP,  WOFS_F);
        wsplit_kernel<<<((long)CL*CD*CD/4 + t-1)/t, t>>>(Wo, pwh, pwl, CD*CD,  WOFS_O);
        wsplit_kernel<<<((long)CL*CD*CDF/4 + t-1)/t, t>>>(W1, pwh, pwl, CD*CDF, WOFS_1);
        wsplit_kernel<<<((long)CL*CDF*CD/4 + t-1)/t, t>>>(W2, pwh, pwl, CDF*CD, WOFS_2);
    }

    embed_kernel<<<CBS, 128>>>(x, emb, pos);

    for (int l = 0; l < CL; l++) {
        const long lw = (long)l * WSTR;
        const __nv_bfloat16 *wqh = pwh+lw+WOFS_Q, *wql = pwl+lw+WOFS_Q;
        const __nv_bfloat16 *wkh = pwh+lw+WOFS_K, *wkl = pwl+lw+WOFS_K;
        const __nv_bfloat16 *wvh = pwh+lw+WOFS_V, *wvl = pwl+lw+WOFS_V;
        const __nv_bfloat16 *wfh = pwh+lw+WOFS_F, *wfl = pwl+lw+WOFS_F;
        const __nv_bfloat16 *woh = pwh+lw+WOFS_O, *wol = pwl+lw+WOFS_O;
        const __nv_bfloat16 *w1h = pwh+lw+WOFS_1, *w1l = pwl+lw+WOFS_1;
        const __nv_bfloat16 *w2h = pwh+lw+WOFS_2, *w2l = pwl+lw+WOFS_2;
        const float* biq = bq + (long)l * CD;
        const float* bik = bk + (long)l * CD;
        const float* biv = bv + (long)l * CD;
        const float* bif = bf + (long)l * CP;
        const float* bio = bo + (long)l * CD;
        const float* bi1 = b1 + (long)l * CDF;
        const float* bi2 = b2 + (long)l * CD;

        dim3 gQKV(CD / 128, CBS / 128, 1);
        bgemm<0,0,1><<<gQKV, 256, SMEM_BG>>>(hbh, hbl, wqh, wql, biq,
                                             nullptr, qbh, qbl, CBS, CD, CD, 0, 0, 0, nullptr);
        bgemm<0,0,1><<<gQKV, 256, SMEM_BG>>>(hbh, hbl, wkh, wkl, bik,
                                             nullptr, kbh, kbl, CBS, CD, CD, 0, 0, 0, nullptr);
        bgemm<0,1,0><<<gQKV, 256, SMEM_BG>>>(hbh, hbl, wvh, wvl, biv,
                                             pv, nullptr, nullptr, CBS, CD, CD, 0, 0, 0, nullptr);

        dim3 gF(CP / 128, CBS / 128, 1);
        bgemm<1,1,1><<<gF, 256, SMEM_BG>>>(qbh, qbl, wfh, wfl, bif,
                                           ppq, pqh, pql, CBS, CP, CD, 0, 0, 0, nullptr);
        bgemm<1,1,0><<<gF, 256, SMEM_BG>>>(kbh, kbl, wfh, wfl, bif,
                                           ppk, nullptr, nullptr, CBS, CP, CD, 0, 0, 0, nullptr);

        pksum_part_kernel<<<dim3(CB, PKCH), 128>>>();
        pksum_reduce_kernel<<<(CB * CP + 255) / 256, 256>>>();

        sgemm_tn_split<<<dim3(CD / 128, 1, CB * KVSPLIT), 256>>>();
        kv_reduce_kernel<<<(CB * CP * CD + 255) / 256, 256>>>();

        z_kernel<<<CBS / 8, 256>>>();

        // out[b,s,d] = (pq @ kv) / (z + eps)   (batched, bf16 planes)
        dim3 gO(CD / 128, CS / 128, CB);
        bgemm<3,0,1><<<gO, 256, SMEM_BG>>>(pqh, pql, kvh, kvl, nullptr,
                                           nullptr, abh, abl, CS, CD, CP,
                                           (long)CS * CP, (long)CP * CD, (long)CS * CD, pz);

        bgemm<0,1,0><<<gQKV, 256, SMEM_BG>>>(abh, abl, woh, wol, bio,
                                             pWoOut, nullptr, nullptr, CBS, CD, CD, 0, 0, 0, nullptr);

        ln_kernel<<<CBS, 128>>>(pWoOut, lng + (long)l * CD, lnb + (long)l * CD);

        dim3 g1(CDF / 128, CBS / 128, 1);
        bgemm<2,0,1><<<g1, 256, SMEM_BG>>>(lnh, lnl, w1h, w1l, bi1,
                                           nullptr, mlph, mlpl, CBS, CDF, CD, 0, 0, 0, nullptr);

        dim3 g2(CD / 128, CBS / 128, 1);
        bgemm<0,1,1><<<g2, 256, SMEM_BG>>>(mlph, mlpl, w2h, w2l, bi2,
                                           ph, hbh, hbl, CBS, CD, CDF, 0, 0, 0, nullptr);
    }

    pool_part_kernel<<<dim3(CB, POOLCH), CD>>>();
    pool_reduce_kernel<<<(CB * CD + 255) / 256, 256>>>();
    head1_kernel<<<CB, CDH>>>(Wh1, bh1);
    head2_kernel<<<1, 32>>>(Wh2, bh2, out);
}